// round 6
// baseline (speedup 1.0000x reference)
#include <cuda_runtime.h>
#include <math.h>
#include <stdint.h>

// Problem constants
#define BB   8
#define DD   64      // FIN
#define NN   2048
#define KK   20      // k neighbors
#define CC   128     // 2*FIN edge-feature channels
#define O1   256     // conv1 out channels
#define J1   10      // conv1 output spatial (20-11+1)
#define T1   11      // conv1 kernel width
#define O2C  256     // conv2 out channels
#define SS   40      // conv2 kernel width (full window)
#define GN   4       // points per knn block
#define G1   8       // points per conv1 block
#define G2P  32      // points per conv2 chunk block
#define CCH  32      // conv2 c-chunk size
#define NCH  4       // conv2 chunk passes
#define RPAD 34      // conv2 smem row stride

typedef unsigned long long ull;

__device__ __forceinline__ ull fma2(ull a, ull b, ull c) {
    ull d;
    asm("fma.rn.f32x2 %0, %1, %2, %3;" : "=l"(d) : "l"(a), "l"(b), "l"(c));
    return d;
}
__device__ __forceinline__ ull dup2(float v) {
    ull d; unsigned int u = __float_as_uint(v);
    asm("mov.b64 %0, {%1, %1};" : "=l"(d) : "r"(u));
    return d;
}
__device__ __forceinline__ float2 unpk(ull v) {
    float2 r;
    asm("mov.b64 {%0, %1}, %2;" : "=f"(r.x), "=f"(r.y) : "l"(v));
    return r;
}

// ---------------- scratch (static device globals; no allocs) ----------------
__device__ float g_sq[BB * NN];
__device__ int   g_idx[BB * NN * KK];
__device__ float g_ee[(size_t)BB * NN * CC * KK];   // [b][n][m=c*20+k]
__device__ float g_h [(size_t)BB * NN * O1 * J1];   // [b][n][o][j]
__device__ float g_bn1a[O1];
__device__ float g_bn1b[O1];
__device__ float g_y [BB * NN * O2C];               // [b][n][o2]
__device__ float g_bn2a[O2C];
__device__ float g_bn2b[O2C];
__device__ float g_w1t[CC * O1 * T1];               // [c][o][t]
__device__ float g_w2t[CC * SS * O2C];              // [c][s][o2]

// ---------------- weight transposes ----------------
__global__ void k_tw1(const float* __restrict__ w1) {
    int i = blockIdx.x * 256 + threadIdx.x;
    if (i >= CC * O1 * T1) return;
    int o = i / (CC * T1);
    int r = i % (CC * T1);
    int c = r / T1, t = r % T1;
    g_w1t[(c * O1 + o) * T1 + t] = w1[i];
}
__global__ void k_tw2(const float* __restrict__ w2) {
    int i = blockIdx.x * 256 + threadIdx.x;
    if (i >= CC * SS * O2C) return;
    int o = i / (CC * SS);
    int r = i % (CC * SS);
    int c = r / SS, s = r % SS;
    g_w2t[(c * SS + s) * O2C + o] = w2[i];
}

// ---------------- kernel 1: squared norms (mul-then-add, matches ref) --------
__global__ void k_sq(const float* __restrict__ x) {
    int i = blockIdx.x * 256 + threadIdx.x;
    if (i >= BB * NN) return;
    int b = i / NN, n = i % NN;
    const float* xb = x + (size_t)b * DD * NN + n;
    float s = 0.f;
#pragma unroll
    for (int d = 0; d < DD; d++) {
        float v = xb[(size_t)d * NN];
        s = __fadd_rn(s, __fmul_rn(v, v));
    }
    g_sq[i] = s;
}

// ---------------- kernel 2: kNN — shuffle-based deterministic top-20 ----------
__global__ void __launch_bounds__(256) k_knn(const float* __restrict__ x) {
    int b  = blockIdx.x / (NN / GN);
    int n0 = (blockIdx.x % (NN / GN)) * GN;
    __shared__ float xn[GN][DD];
    __shared__ float dist[GN][NN];
    __shared__ float wv[8];
    __shared__ int   wi[8];
    __shared__ int   wins;
    int tid = threadIdx.x;
    int wid = tid >> 5, lane = tid & 31;

    const float* xb = x + (size_t)b * DD * NN;
    for (int i = tid; i < GN * DD; i += 256) {
        int g = i / DD, d = i % DD;
        xn[g][d] = xb[(size_t)d * NN + n0 + g];
    }
    __syncthreads();

    float sqn[GN];
#pragma unroll
    for (int g = 0; g < GN; g++) sqn[g] = g_sq[b * NN + n0 + g];

    float dot[GN][8];
#pragma unroll
    for (int g = 0; g < GN; g++)
#pragma unroll
        for (int i = 0; i < 8; i++) dot[g][i] = 0.f;

    for (int d = 0; d < DD; d++) {
        float xv[8];
#pragma unroll
        for (int i = 0; i < 8; i++) xv[i] = xb[(size_t)d * NN + tid + 256 * i];
#pragma unroll
        for (int g = 0; g < GN; g++) {
            float xnv = xn[g][d];
#pragma unroll
            for (int i = 0; i < 8; i++) dot[g][i] = __fmaf_rn(xnv, xv[i], dot[g][i]);
        }
    }
#pragma unroll
    for (int i = 0; i < 8; i++) {
        int m = tid + 256 * i;
        float sm = g_sq[b * NN + m];
#pragma unroll
        for (int g = 0; g < GN; g++) {
            float t  = __fadd_rn(sqn[g], sm);
            float u  = __fmul_rn(2.f, dot[g][i]);
            float dv = __fsub_rn(t, u);
            dist[g][m] = (m == n0 + g) ? 1e30f : dv;
        }
    }
    __syncthreads();

    for (int g = 0; g < GN; g++) {
        // per-thread best over own 8 strided elements (lowest index wins ties)
        float bv = 1e30f; int bi = 1 << 29;
#pragma unroll
        for (int i = 0; i < 8; i++) {
            int m = tid + 256 * i;
            float v = dist[g][m];
            if (v < bv || (v == bv && m < bi)) { bv = v; bi = m; }
        }
        for (int kk = 0; kk < KK; kk++) {
            float v = bv; int idx = bi;
#pragma unroll
            for (int s = 16; s; s >>= 1) {
                float vo = __shfl_xor_sync(0xffffffffu, v, s);
                int   io = __shfl_xor_sync(0xffffffffu, idx, s);
                if (vo < v || (vo == v && io < idx)) { v = vo; idx = io; }
            }
            if (lane == 0) { wv[wid] = v; wi[wid] = idx; }
            __syncthreads();
            if (wid == 0) {
                float v2 = (lane < 8) ? wv[lane] : 1e30f;
                int   i2 = (lane < 8) ? wi[lane] : (1 << 29);
#pragma unroll
                for (int s = 4; s; s >>= 1) {
                    float vo = __shfl_xor_sync(0xffffffffu, v2, s);
                    int   io = __shfl_xor_sync(0xffffffffu, i2, s);
                    if (vo < v2 || (vo == v2 && io < i2)) { v2 = vo; i2 = io; }
                }
                if (lane == 0) {
                    wins = i2;
                    g_idx[(b * NN + n0 + g) * KK + kk] = i2;
                }
            }
            __syncthreads();
            int w = wins;
            if ((w & 255) == tid) {       // owner removes winner + rescans its 8
                dist[g][w] = 1e30f;
                bv = 1e30f; bi = 1 << 29;
#pragma unroll
                for (int i = 0; i < 8; i++) {
                    int m = tid + 256 * i;
                    float vv = dist[g][m];
                    if (vv < bv || (vv == bv && m < bi)) { bv = vv; bi = m; }
                }
            }
        }
    }
}

// ---------------- kernel 3: edge features + conv1 (512 thr, 8 points) --------
// dyn smem: ee_s[2560][8] (80KB) + w_s[2][O1*T1] (22.5KB) = 102KB
__global__ void __launch_bounds__(512, 1) k_conv1(const float* __restrict__ x,
                                                  const float* __restrict__ b1) {
    extern __shared__ float smem[];
    float* ee_s = smem;                   // [m = c*20+k][g], stride G1=8
    float* w_s  = smem + CC * KK * G1;    // [2][O1*T1]
    int b  = blockIdx.x / (NN / G1);
    int n0 = (blockIdx.x % (NN / G1)) * G1;
    int tid = threadIdx.x;
    int o = tid & 255;
    int half = tid >> 8;                  // 0: points 0-3, 1: points 4-7
    const float* xb = x + (size_t)b * DD * NN;

    for (int i = tid; i < G1 * CC * KK; i += 512) {
        int g = i & 7;
        int m = i >> 3;
        int c = m / KK, k = m % KK;
        int n = n0 + g;
        float v;
        if (c < DD) {
            v = xb[(size_t)c * NN + n];
        } else {
            int mm = g_idx[(b * NN + n) * KK + k];
            int d = c - DD;
            v = xb[(size_t)d * NN + mm] - xb[(size_t)d * NN + n];
        }
        ee_s[i] = v;                                   // linear store, no conflicts
        g_ee[(size_t)(b * NN + n) * (CC * KK) + m] = v;
    }
    for (int i = tid; i < O1 * T1; i += 512) w_s[i] = g_w1t[i];
    __syncthreads();

    ull acc[2][J1];
#pragma unroll
    for (int p = 0; p < 2; p++)
#pragma unroll
        for (int j = 0; j < J1; j++) acc[p][j] = 0ull;

    for (int c = 0; c < CC; c++) {
        int cur = c & 1;
        if (c + 1 < CC) {
            const float* src = &g_w1t[(c + 1) * (O1 * T1)];
            float* dst = &w_s[(cur ^ 1) * (O1 * T1)];
            for (int i = tid; i < O1 * T1; i += 512) dst[i] = src[i];
        }
        ull wd[T1];
#pragma unroll
        for (int t = 0; t < T1; t++) wd[t] = dup2(w_s[cur * (O1 * T1) + o * T1 + t]);
        const float* ers = &ee_s[c * KK * G1];
#pragma unroll
        for (int p = 0; p < 2; p++) {
            int gbase = half * 4 + 2 * p;
            ull e[KK];
#pragma unroll
            for (int k = 0; k < KK; k++)
                e[k] = *(const ull*)&ers[k * G1 + gbase];   // broadcast LDS.64
#pragma unroll
            for (int j = 0; j < J1; j++)
#pragma unroll
                for (int t = 0; t < T1; t++)
                    acc[p][j] = fma2(e[j + t], wd[t], acc[p][j]);
        }
        __syncthreads();
    }
    float bias = b1[o];
#pragma unroll
    for (int p = 0; p < 2; p++) {
        int g0 = half * 4 + 2 * p;
#pragma unroll
        for (int j = 0; j < J1; j++) {
            float2 v = unpk(acc[p][j]);
            g_h[((size_t)(b * NN + n0 + g0)     * O1 + o) * J1 + j] = v.x + bias;
            g_h[((size_t)(b * NN + n0 + g0 + 1) * O1 + o) * J1 + j] = v.y + bias;
        }
    }
}

// ---------------- kernel 4: BN1 stats ----------------
__global__ void k_bn1(const float* __restrict__ gamma, const float* __restrict__ beta) {
    int o = blockIdx.x;
    int tid = threadIdx.x;
    float s = 0.f, s2 = 0.f;
    for (int p = tid; p < BB * NN; p += 256) {
        const float* hp = &g_h[((size_t)p * O1 + o) * J1];
#pragma unroll
        for (int j = 0; j < J1; j++) { float v = hp[j]; s += v; s2 += v * v; }
    }
    __shared__ float rs[256], rs2[256];
    rs[tid] = s; rs2[tid] = s2;
    __syncthreads();
    for (int t = 128; t > 0; t >>= 1) {
        if (tid < t) { rs[tid] += rs[tid + t]; rs2[tid] += rs2[tid + t]; }
        __syncthreads();
    }
    if (tid == 0) {
        float cnt  = (float)(BB * NN * J1);
        float mean = rs[0] / cnt;
        float var  = rs2[0] / cnt - mean * mean;
        float a    = gamma[o] * rsqrtf(var + 1e-5f);
        g_bn1a[o] = a;
        g_bn1b[o] = beta[o] - mean * a;
    }
}

// ---------------- kernel 5: conv2, c-chunked ----------------
__global__ void __launch_bounds__(256) k_conv2c(const float* __restrict__ b2, int pass) {
    extern __shared__ float smem[];
    float* ee2 = smem;                    // [cl*20+k][g] stride RPAD
    float* hp2 = smem + CCH * KK * RPAD;
    int b  = blockIdx.x / (NN / G2P);
    int n0 = (blockIdx.x % (NN / G2P)) * G2P;
    int c0 = pass * CCH;
    int tid = threadIdx.x;

    for (int i = tid; i < G2P * CCH * KK; i += 256) {
        int g = i / (CCH * KK);
        int m = i % (CCH * KK);
        ee2[m * RPAD + g] = g_ee[(size_t)(b * NN + n0 + g) * (CC * KK) + c0 * KK + m];
    }
    for (int i = tid; i < G2P * CCH * KK; i += 256) {
        int g = i / (CCH * KK);
        int m = i % (CCH * KK);
        int lin = c0 * KK + m;
        int o = lin / J1;
        float raw = g_h[(size_t)(b * NN + n0 + g) * (O1 * J1) + lin];
        float v = g_bn1a[o] * raw + g_bn1b[o];
        hp2[m * RPAD + g] = v > 0.f ? v : 0.01f * v;
    }
    __syncthreads();

    int o2 = tid;
    ull acc[G2P / 2];
#pragma unroll
    for (int p = 0; p < G2P / 2; p++) acc[p] = 0ull;

    for (int cl = 0; cl < CCH; cl++) {
        const float* wrow = &g_w2t[((c0 + cl) * SS) * O2C + o2];
        const float* er = &ee2[cl * KK * RPAD];
        const float* hr = &hp2[cl * KK * RPAD];
#pragma unroll 4
        for (int s = 0; s < KK; s++) {
            ull wd = dup2(wrow[s * O2C]);
            const float* row = &er[s * RPAD];
#pragma unroll
            for (int p = 0; p < G2P / 2; p++)
                acc[p] = fma2(*(const ull*)&row[2 * p], wd, acc[p]);
        }
#pragma unroll 4
        for (int s = 0; s < KK; s++) {
            ull wd = dup2(wrow[(KK + s) * O2C]);
            const float* row = &hr[s * RPAD];
#pragma unroll
            for (int p = 0; p < G2P / 2; p++)
                acc[p] = fma2(*(const ull*)&row[2 * p], wd, acc[p]);
        }
    }

    if (pass == 0) {
        float bias = b2[o2];
#pragma unroll
        for (int p = 0; p < G2P / 2; p++) {
            float2 v = unpk(acc[p]);
            g_y[(b * NN + n0 + 2 * p)     * O2C + o2] = v.x + bias;
            g_y[(b * NN + n0 + 2 * p + 1) * O2C + o2] = v.y + bias;
        }
    } else {
#pragma unroll
        for (int p = 0; p < G2P / 2; p++) {
            float2 v = unpk(acc[p]);
            g_y[(b * NN + n0 + 2 * p)     * O2C + o2] += v.x;
            g_y[(b * NN + n0 + 2 * p + 1) * O2C + o2] += v.y;
        }
    }
}

// ---------------- kernel 6: BN2 stats ----------------
__global__ void k_bn2(const float* __restrict__ gamma, const float* __restrict__ beta) {
    int o = blockIdx.x;
    int tid = threadIdx.x;
    float s = 0.f, s2 = 0.f;
    for (int p = tid; p < BB * NN; p += 256) {
        float v = g_y[(size_t)p * O2C + o];
        s += v; s2 += v * v;
    }
    __shared__ float rs[256], rs2[256];
    rs[tid] = s; rs2[tid] = s2;
    __syncthreads();
    for (int t = 128; t > 0; t >>= 1) {
        if (tid < t) { rs[tid] += rs[tid + t]; rs2[tid] += rs2[tid + t]; }
        __syncthreads();
    }
    if (tid == 0) {
        float cnt  = (float)(BB * NN);
        float mean = rs[0] / cnt;
        float var  = rs2[0] / cnt - mean * mean;
        float a    = gamma[o] * rsqrtf(var + 1e-5f);
        g_bn2a[o] = a;
        g_bn2b[o] = beta[o] - mean * a;
    }
}

// ---------------- kernel 7: BN2 apply + relu + reshape ----------------
__global__ void k_out(float* __restrict__ out) {
    int i = blockIdx.x * 256 + threadIdx.x;
    if (i >= BB * 128 * 4096) return;
    int b = i >> 19;
    int r = i & 524287;
    int f = r >> 12;
    int m = r & 4095;
    int o2 = f * 2 + (m >> 11);
    int n  = m & 2047;
    float v = g_bn2a[o2] * g_y[(b * NN + n) * O2C + o2] + g_bn2b[o2];
    out[i] = v > 0.f ? v : 0.f;
}

// ---------------- launch ----------------
extern "C" void kernel_launch(void* const* d_in, const int* in_sizes, int n_in,
                              void* d_out, int out_size) {
    const float* x   = (const float*)d_in[0];
    const float* w1  = (const float*)d_in[1];
    const float* b1  = (const float*)d_in[2];
    const float* g1  = (const float*)d_in[3];
    const float* be1 = (const float*)d_in[4];
    const float* w2  = (const float*)d_in[5];
    const float* b2  = (const float*)d_in[6];
    const float* g2  = (const float*)d_in[7];
    const float* be2 = (const float*)d_in[8];
    float* out = (float*)d_out;

    static int attr_done = 0;
    int smem1 = (CC * KK * G1 + 2 * O1 * T1) * (int)sizeof(float);       // 102KB
    int smem2 = (2 * CCH * KK * RPAD) * (int)sizeof(float);              // 174KB
    if (!attr_done) {
        cudaFuncSetAttribute(k_conv1,  cudaFuncAttributeMaxDynamicSharedMemorySize, smem1);
        cudaFuncSetAttribute(k_conv2c, cudaFuncAttributeMaxDynamicSharedMemorySize, smem2);
        attr_done = 1;
    }

    k_tw1 <<<(CC * O1 * T1 + 255) / 256, 256>>>(w1);
    k_tw2 <<<(CC * SS * O2C + 255) / 256, 256>>>(w2);
    k_sq  <<<(BB * NN + 255) / 256, 256>>>(x);
    k_knn <<<BB * NN / GN, 256>>>(x);
    k_conv1<<<BB * NN / G1, 512, smem1>>>(x, b1);
    k_bn1 <<<O1, 256>>>(g1, be1);
    for (int p = 0; p < NCH; p++)
        k_conv2c<<<BB * NN / G2P, 256, smem2>>>(b2, p);
    k_bn2 <<<O2C, 256>>>(g2, be2);
    k_out <<<(BB * 128 * 4096) / 256, 256>>>(out);
}

// round 7
// speedup vs baseline: 1.1984x; 1.1984x over previous
#include <cuda_runtime.h>
#include <math.h>
#include <stdint.h>

// Problem constants
#define BB   8
#define DD   64      // FIN
#define NN   2048
#define KK   20      // k neighbors
#define CC   128     // 2*FIN edge-feature channels
#define O1   256     // conv1 out channels
#define J1   10      // conv1 output spatial (20-11+1)
#define T1   11      // conv1 kernel width
#define O2C  256     // conv2 out channels
#define SS   40      // conv2 kernel width (full window)
#define GN   4       // points per knn block
#define G1   4       // points per conv1 block
#define G2P  32      // points per conv2 chunk block
#define CCH  32      // conv2 c-chunk size
#define NCH  4       // conv2 chunk passes
#define RPAD 34      // conv2 smem row stride
#define W1SLAB (O1 * T1)   // 2816 floats per conv1 input channel

typedef unsigned long long ull;

__device__ __forceinline__ ull fma2(ull a, ull b, ull c) {
    ull d;
    asm("fma.rn.f32x2 %0, %1, %2, %3;" : "=l"(d) : "l"(a), "l"(b), "l"(c));
    return d;
}
__device__ __forceinline__ ull dup2(float v) {
    ull d; unsigned int u = __float_as_uint(v);
    asm("mov.b64 %0, {%1, %1};" : "=l"(d) : "r"(u));
    return d;
}
__device__ __forceinline__ float2 unpk(ull v) {
    float2 r;
    asm("mov.b64 {%0, %1}, %2;" : "=f"(r.x), "=f"(r.y) : "l"(v));
    return r;
}

// ---------------- scratch (static device globals; no allocs) ----------------
__device__ float g_sq[BB * NN];
__device__ int   g_idx[BB * NN * KK];
__device__ float g_ee[(size_t)BB * NN * CC * KK];   // [b][n][m=c*20+k]
__device__ float g_h [(size_t)BB * NN * O1 * J1];   // [b][n][o][j]
__device__ float g_bn1a[O1];
__device__ float g_bn1b[O1];
__device__ float g_y [BB * NN * O2C];               // [b][n][o2]
__device__ float g_bn2a[O2C];
__device__ float g_bn2b[O2C];
__device__ float g_w1t[CC * O1 * T1];               // [c][o][t]
__device__ float g_w2t[CC * SS * O2C];              // [c][s][o2]

// ---------------- weight transposes ----------------
__global__ void k_tw1(const float* __restrict__ w1) {
    int i = blockIdx.x * 256 + threadIdx.x;
    if (i >= CC * O1 * T1) return;
    int o = i / (CC * T1);
    int r = i % (CC * T1);
    int c = r / T1, t = r % T1;
    g_w1t[(c * O1 + o) * T1 + t] = w1[i];
}
__global__ void k_tw2(const float* __restrict__ w2) {
    int i = blockIdx.x * 256 + threadIdx.x;
    if (i >= CC * SS * O2C) return;
    int o = i / (CC * SS);
    int r = i % (CC * SS);
    int c = r / SS, s = r % SS;
    g_w2t[(c * SS + s) * O2C + o] = w2[i];
}

// ---------------- kernel 1: squared norms (mul-then-add, matches ref) --------
__global__ void k_sq(const float* __restrict__ x) {
    int i = blockIdx.x * 256 + threadIdx.x;
    if (i >= BB * NN) return;
    int b = i / NN, n = i % NN;
    const float* xb = x + (size_t)b * DD * NN + n;
    float s = 0.f;
#pragma unroll
    for (int d = 0; d < DD; d++) {
        float v = xb[(size_t)d * NN];
        s = __fadd_rn(s, __fmul_rn(v, v));
    }
    g_sq[i] = s;
}

// ---------------- kernel 2: kNN — shuffle-based deterministic top-20 ----------
__global__ void __launch_bounds__(256) k_knn(const float* __restrict__ x) {
    int b  = blockIdx.x / (NN / GN);
    int n0 = (blockIdx.x % (NN / GN)) * GN;
    __shared__ float xn[GN][DD];
    __shared__ float dist[GN][NN];
    __shared__ float wv[8];
    __shared__ int   wi[8];
    __shared__ int   wins;
    int tid = threadIdx.x;
    int wid = tid >> 5, lane = tid & 31;

    const float* xb = x + (size_t)b * DD * NN;
    for (int i = tid; i < GN * DD; i += 256) {
        int g = i / DD, d = i % DD;
        xn[g][d] = xb[(size_t)d * NN + n0 + g];
    }
    __syncthreads();

    float sqn[GN];
#pragma unroll
    for (int g = 0; g < GN; g++) sqn[g] = g_sq[b * NN + n0 + g];

    float dot[GN][8];
#pragma unroll
    for (int g = 0; g < GN; g++)
#pragma unroll
        for (int i = 0; i < 8; i++) dot[g][i] = 0.f;

    for (int d = 0; d < DD; d++) {
        float xv[8];
#pragma unroll
        for (int i = 0; i < 8; i++) xv[i] = xb[(size_t)d * NN + tid + 256 * i];
#pragma unroll
        for (int g = 0; g < GN; g++) {
            float xnv = xn[g][d];
#pragma unroll
            for (int i = 0; i < 8; i++) dot[g][i] = __fmaf_rn(xnv, xv[i], dot[g][i]);
        }
    }
#pragma unroll
    for (int i = 0; i < 8; i++) {
        int m = tid + 256 * i;
        float sm = g_sq[b * NN + m];
#pragma unroll
        for (int g = 0; g < GN; g++) {
            float t  = __fadd_rn(sqn[g], sm);
            float u  = __fmul_rn(2.f, dot[g][i]);
            float dv = __fsub_rn(t, u);
            dist[g][m] = (m == n0 + g) ? 1e30f : dv;
        }
    }
    __syncthreads();

    for (int g = 0; g < GN; g++) {
        float bv = 1e30f; int bi = 1 << 29;
#pragma unroll
        for (int i = 0; i < 8; i++) {
            int m = tid + 256 * i;
            float v = dist[g][m];
            if (v < bv || (v == bv && m < bi)) { bv = v; bi = m; }
        }
        for (int kk = 0; kk < KK; kk++) {
            float v = bv; int idx = bi;
#pragma unroll
            for (int s = 16; s; s >>= 1) {
                float vo = __shfl_xor_sync(0xffffffffu, v, s);
                int   io = __shfl_xor_sync(0xffffffffu, idx, s);
                if (vo < v || (vo == v && io < idx)) { v = vo; idx = io; }
            }
            if (lane == 0) { wv[wid] = v; wi[wid] = idx; }
            __syncthreads();
            if (wid == 0) {
                float v2 = (lane < 8) ? wv[lane] : 1e30f;
                int   i2 = (lane < 8) ? wi[lane] : (1 << 29);
#pragma unroll
                for (int s = 4; s; s >>= 1) {
                    float vo = __shfl_xor_sync(0xffffffffu, v2, s);
                    int   io = __shfl_xor_sync(0xffffffffu, i2, s);
                    if (vo < v2 || (vo == v2 && io < i2)) { v2 = vo; i2 = io; }
                }
                if (lane == 0) {
                    wins = i2;
                    g_idx[(b * NN + n0 + g) * KK + kk] = i2;
                }
            }
            __syncthreads();
            int w = wins;
            if ((w & 255) == tid) {
                dist[g][w] = 1e30f;
                bv = 1e30f; bi = 1 << 29;
#pragma unroll
                for (int i = 0; i < 8; i++) {
                    int m = tid + 256 * i;
                    float vv = dist[g][m];
                    if (vv < bv || (vv == bv && m < bi)) { bv = vv; bi = m; }
                }
            }
        }
    }
}

// ---------------- kernel 3: edge features + conv1 ----------------
// 256 threads, G1=4 points, 2 blocks/SM forced.
// dyn smem: ee_s[2560][4] (40KB) + w_s[2 buf][2 slabs][2816] (44KB) = 84KB
__global__ void __launch_bounds__(256, 2) k_conv1(const float* __restrict__ x,
                                                  const float* __restrict__ b1) {
    extern __shared__ float smem[];
    float* ee_s = smem;                   // [m = c*20+k][g], stride G1=4
    float* w_s  = smem + CC * KK * G1;    // [2][2*W1SLAB]
    int b  = blockIdx.x / (NN / G1);
    int n0 = (blockIdx.x % (NN / G1)) * G1;
    int tid = threadIdx.x;
    const float* xb = x + (size_t)b * DD * NN;

    for (int i = tid; i < G1 * CC * KK; i += 256) {
        int g = i & 3;
        int m = i >> 2;
        int c = m / KK, k = m % KK;
        int n = n0 + g;
        float v;
        if (c < DD) {
            v = xb[(size_t)c * NN + n];
        } else {
            int mm = g_idx[(b * NN + n) * KK + k];
            int d = c - DD;
            v = xb[(size_t)d * NN + mm] - xb[(size_t)d * NN + n];
        }
        ee_s[i] = v;
        g_ee[(size_t)(b * NN + n) * (CC * KK) + m] = v;
    }
    // preload weights for c=0,1 into buffer 0 (float4 copies)
    {
        const float4* src = (const float4*)g_w1t;
        float4* dst = (float4*)w_s;
        for (int i = tid; i < 2 * W1SLAB / 4; i += 256) dst[i] = src[i];
    }
    __syncthreads();

    int o = tid;
    ull acc[2][J1];
#pragma unroll
    for (int p = 0; p < 2; p++)
#pragma unroll
        for (int j = 0; j < J1; j++) acc[p][j] = 0ull;

    for (int cc0 = 0; cc0 < CC; cc0 += 2) {
        int cur = (cc0 >> 1) & 1;
        if (cc0 + 2 < CC) {
            const float4* src = (const float4*)&g_w1t[(cc0 + 2) * W1SLAB];
            float4* dst = (float4*)&w_s[(cur ^ 1) * (2 * W1SLAB)];
            for (int i = tid; i < 2 * W1SLAB / 4; i += 256) dst[i] = src[i];
        }
#pragma unroll
        for (int dc = 0; dc < 2; dc++) {
            int c = cc0 + dc;
            ull wd[T1];
#pragma unroll
            for (int t = 0; t < T1; t++)
                wd[t] = dup2(w_s[cur * (2 * W1SLAB) + dc * W1SLAB + o * T1 + t]);
            const float* ers = &ee_s[c * KK * G1];
#pragma unroll
            for (int p = 0; p < 2; p++) {
                ull e[KK];
#pragma unroll
                for (int k = 0; k < KK; k++)
                    e[k] = *(const ull*)&ers[k * G1 + 2 * p];   // broadcast LDS.64
#pragma unroll
                for (int j = 0; j < J1; j++)
#pragma unroll
                    for (int t = 0; t < T1; t++)
                        acc[p][j] = fma2(e[j + t], wd[t], acc[p][j]);
            }
        }
        __syncthreads();
    }
    float bias = b1[o];
#pragma unroll
    for (int p = 0; p < 2; p++)
#pragma unroll
        for (int j = 0; j < J1; j++) {
            float2 v = unpk(acc[p][j]);
            g_h[((size_t)(b * NN + n0 + 2 * p)     * O1 + o) * J1 + j] = v.x + bias;
            g_h[((size_t)(b * NN + n0 + 2 * p + 1) * O1 + o) * J1 + j] = v.y + bias;
        }
}

// ---------------- kernel 4: BN1 stats ----------------
__global__ void k_bn1(const float* __restrict__ gamma, const float* __restrict__ beta) {
    int o = blockIdx.x;
    int tid = threadIdx.x;
    float s = 0.f, s2 = 0.f;
    for (int p = tid; p < BB * NN; p += 256) {
        const float* hp = &g_h[((size_t)p * O1 + o) * J1];
#pragma unroll
        for (int j = 0; j < J1; j++) { float v = hp[j]; s += v; s2 += v * v; }
    }
    __shared__ float rs[256], rs2[256];
    rs[tid] = s; rs2[tid] = s2;
    __syncthreads();
    for (int t = 128; t > 0; t >>= 1) {
        if (tid < t) { rs[tid] += rs[tid + t]; rs2[tid] += rs2[tid + t]; }
        __syncthreads();
    }
    if (tid == 0) {
        float cnt  = (float)(BB * NN * J1);
        float mean = rs[0] / cnt;
        float var  = rs2[0] / cnt - mean * mean;
        float a    = gamma[o] * rsqrtf(var + 1e-5f);
        g_bn1a[o] = a;
        g_bn1b[o] = beta[o] - mean * a;
    }
}

// ---------------- kernel 5: conv2, c-chunked ----------------
__global__ void __launch_bounds__(256) k_conv2c(const float* __restrict__ b2, int pass) {
    extern __shared__ float smem[];
    float* ee2 = smem;                    // [cl*20+k][g] stride RPAD
    float* hp2 = smem + CCH * KK * RPAD;
    int b  = blockIdx.x / (NN / G2P);
    int n0 = (blockIdx.x % (NN / G2P)) * G2P;
    int c0 = pass * CCH;
    int tid = threadIdx.x;

    for (int i = tid; i < G2P * CCH * KK; i += 256) {
        int g = i / (CCH * KK);
        int m = i % (CCH * KK);
        ee2[m * RPAD + g] = g_ee[(size_t)(b * NN + n0 + g) * (CC * KK) + c0 * KK + m];
    }
    for (int i = tid; i < G2P * CCH * KK; i += 256) {
        int g = i / (CCH * KK);
        int m = i % (CCH * KK);
        int lin = c0 * KK + m;
        int o = lin / J1;
        float raw = g_h[(size_t)(b * NN + n0 + g) * (O1 * J1) + lin];
        float v = g_bn1a[o] * raw + g_bn1b[o];
        hp2[m * RPAD + g] = v > 0.f ? v : 0.01f * v;
    }
    __syncthreads();

    int o2 = tid;
    ull acc[G2P / 2];
#pragma unroll
    for (int p = 0; p < G2P / 2; p++) acc[p] = 0ull;

    for (int cl = 0; cl < CCH; cl++) {
        const float* wrow = &g_w2t[((c0 + cl) * SS) * O2C + o2];
        const float* er = &ee2[cl * KK * RPAD];
        const float* hr = &hp2[cl * KK * RPAD];
#pragma unroll 4
        for (int s = 0; s < KK; s++) {
            ull wd = dup2(wrow[s * O2C]);
            const float* row = &er[s * RPAD];
#pragma unroll
            for (int p = 0; p < G2P / 2; p++)
                acc[p] = fma2(*(const ull*)&row[2 * p], wd, acc[p]);
        }
#pragma unroll 4
        for (int s = 0; s < KK; s++) {
            ull wd = dup2(wrow[(KK + s) * O2C]);
            const float* row = &hr[s * RPAD];
#pragma unroll
            for (int p = 0; p < G2P / 2; p++)
                acc[p] = fma2(*(const ull*)&row[2 * p], wd, acc[p]);
        }
    }

    if (pass == 0) {
        float bias = b2[o2];
#pragma unroll
        for (int p = 0; p < G2P / 2; p++) {
            float2 v = unpk(acc[p]);
            g_y[(b * NN + n0 + 2 * p)     * O2C + o2] = v.x + bias;
            g_y[(b * NN + n0 + 2 * p + 1) * O2C + o2] = v.y + bias;
        }
    } else {
#pragma unroll
        for (int p = 0; p < G2P / 2; p++) {
            float2 v = unpk(acc[p]);
            g_y[(b * NN + n0 + 2 * p)     * O2C + o2] += v.x;
            g_y[(b * NN + n0 + 2 * p + 1) * O2C + o2] += v.y;
        }
    }
}

// ---------------- kernel 6: BN2 stats ----------------
__global__ void k_bn2(const float* __restrict__ gamma, const float* __restrict__ beta) {
    int o = blockIdx.x;
    int tid = threadIdx.x;
    float s = 0.f, s2 = 0.f;
    for (int p = tid; p < BB * NN; p += 256) {
        float v = g_y[(size_t)p * O2C + o];
        s += v; s2 += v * v;
    }
    __shared__ float rs[256], rs2[256];
    rs[tid] = s; rs2[tid] = s2;
    __syncthreads();
    for (int t = 128; t > 0; t >>= 1) {
        if (tid < t) { rs[tid] += rs[tid + t]; rs2[tid] += rs2[tid + t]; }
        __syncthreads();
    }
    if (tid == 0) {
        float cnt  = (float)(BB * NN);
        float mean = rs[0] / cnt;
        float var  = rs2[0] / cnt - mean * mean;
        float a    = gamma[o] * rsqrtf(var + 1e-5f);
        g_bn2a[o] = a;
        g_bn2b[o] = beta[o] - mean * a;
    }
}

// ---------------- kernel 7: BN2 apply + relu + reshape ----------------
__global__ void k_out(float* __restrict__ out) {
    int i = blockIdx.x * 256 + threadIdx.x;
    if (i >= BB * 128 * 4096) return;
    int b = i >> 19;
    int r = i & 524287;
    int f = r >> 12;
    int m = r & 4095;
    int o2 = f * 2 + (m >> 11);
    int n  = m & 2047;
    float v = g_bn2a[o2] * g_y[(b * NN + n) * O2C + o2] + g_bn2b[o2];
    out[i] = v > 0.f ? v : 0.f;
}

// ---------------- launch ----------------
extern "C" void kernel_launch(void* const* d_in, const int* in_sizes, int n_in,
                              void* d_out, int out_size) {
    const float* x   = (const float*)d_in[0];
    const float* w1  = (const float*)d_in[1];
    const float* b1  = (const float*)d_in[2];
    const float* g1  = (const float*)d_in[3];
    const float* be1 = (const float*)d_in[4];
    const float* w2  = (const float*)d_in[5];
    const float* b2  = (const float*)d_in[6];
    const float* g2  = (const float*)d_in[7];
    const float* be2 = (const float*)d_in[8];
    float* out = (float*)d_out;

    static int attr_done = 0;
    int smem1 = (CC * KK * G1 + 4 * W1SLAB) * (int)sizeof(float);        // 84KB
    int smem2 = (2 * CCH * KK * RPAD) * (int)sizeof(float);              // 174KB
    if (!attr_done) {
        cudaFuncSetAttribute(k_conv1,  cudaFuncAttributeMaxDynamicSharedMemorySize, smem1);
        cudaFuncSetAttribute(k_conv2c, cudaFuncAttributeMaxDynamicSharedMemorySize, smem2);
        attr_done = 1;
    }

    k_tw1 <<<(CC * O1 * T1 + 255) / 256, 256>>>(w1);
    k_tw2 <<<(CC * SS * O2C + 255) / 256, 256>>>(w2);
    k_sq  <<<(BB * NN + 255) / 256, 256>>>(x);
    k_knn <<<BB * NN / GN, 256>>>(x);
    k_conv1<<<BB * NN / G1, 256, smem1>>>(x, b1);
    k_bn1 <<<O1, 256>>>(g1, be1);
    for (int p = 0; p < NCH; p++)
        k_conv2c<<<BB * NN / G2P, 256, smem2>>>(b2, p);
    k_bn2 <<<O2C, 256>>>(g2, be2);
    k_out <<<(BB * 128 * 4096) / 256, 256>>>(out);
}

// round 8
// speedup vs baseline: 1.2870x; 1.0740x over previous
#include <cuda_runtime.h>
#include <math.h>
#include <stdint.h>

// Problem constants
#define BB   8
#define DD   64      // FIN
#define NN   2048
#define KK   20      // k neighbors
#define CC   128     // 2*FIN edge-feature channels
#define O1   256     // conv1 out channels
#define J1   10      // conv1 output spatial (20-11+1)
#define T1   11      // conv1 kernel width
#define O2C  256     // conv2 out channels
#define SS   40      // conv2 kernel width (full window)
#define GN   4       // points per knn block
#define G1   4       // points per conv1 block
#define G2P  32      // points per conv2 chunk block
#define CCH  32      // conv2 c-chunk size
#define NCH  4       // conv2 chunk passes
#define RPAD 34      // conv2 smem row stride
#define W1SLAB (O1 * T1)   // 2816 floats per conv1 input channel
#define NB1  (BB * NN / G1)    // 4096 conv1 blocks
#define NB2  (BB * NN / G2P)   // 512 conv2 blocks per pass

typedef unsigned long long ull;

__device__ __forceinline__ ull fma2(ull a, ull b, ull c) {
    ull d;
    asm("fma.rn.f32x2 %0, %1, %2, %3;" : "=l"(d) : "l"(a), "l"(b), "l"(c));
    return d;
}
__device__ __forceinline__ ull dup2(float v) {
    ull d; unsigned int u = __float_as_uint(v);
    asm("mov.b64 %0, {%1, %1};" : "=l"(d) : "r"(u));
    return d;
}
__device__ __forceinline__ float2 unpk(ull v) {
    float2 r;
    asm("mov.b64 {%0, %1}, %2;" : "=f"(r.x), "=f"(r.y) : "l"(v));
    return r;
}

// ---------------- scratch (static device globals; no allocs) ----------------
__device__ float g_sq[BB * NN];
__device__ int   g_idx[BB * NN * KK];
__device__ float g_ee[(size_t)BB * NN * CC * KK];   // [b][n][m=c*20+k]
__device__ float g_h [(size_t)BB * NN * O1 * J1];   // [b][n][o][j]
__device__ float g_bn1a[O1];
__device__ float g_bn1b[O1];
__device__ float g_y [BB * NN * O2C];               // [b][n][o2]
__device__ float g_bn2a[O2C];
__device__ float g_bn2b[O2C];
__device__ float g_w1t[CC * O1 * T1];               // [c][o][t]
__device__ float g_w2t[CC * SS * O2C];              // [c][s][o2]
__device__ float g_p1[NB1 * O1];                    // conv1 per-block BN partials
__device__ float g_p2[NB1 * O1];
__device__ float g_q1[NB2 * O2C];                   // conv2 per-block BN partials
__device__ float g_q2[NB2 * O2C];

// ---------------- weight transposes ----------------
__global__ void k_tw1(const float* __restrict__ w1) {
    int i = blockIdx.x * 256 + threadIdx.x;
    if (i >= CC * O1 * T1) return;
    int o = i / (CC * T1);
    int r = i % (CC * T1);
    int c = r / T1, t = r % T1;
    g_w1t[(c * O1 + o) * T1 + t] = w1[i];
}
__global__ void k_tw2(const float* __restrict__ w2) {
    int i = blockIdx.x * 256 + threadIdx.x;
    if (i >= CC * SS * O2C) return;
    int o = i / (CC * SS);
    int r = i % (CC * SS);
    int c = r / SS, s = r % SS;
    g_w2t[(c * SS + s) * O2C + o] = w2[i];
}

// ---------------- kernel 1: squared norms (mul-then-add, matches ref) --------
__global__ void k_sq(const float* __restrict__ x) {
    int i = blockIdx.x * 256 + threadIdx.x;
    if (i >= BB * NN) return;
    int b = i / NN, n = i % NN;
    const float* xb = x + (size_t)b * DD * NN + n;
    float s = 0.f;
#pragma unroll
    for (int d = 0; d < DD; d++) {
        float v = xb[(size_t)d * NN];
        s = __fadd_rn(s, __fmul_rn(v, v));
    }
    g_sq[i] = s;
}

// ---------------- kernel 2: kNN — float4 loads + shuffle top-20 --------------
// thread owns m in {4*tid+r, 1024+4*tid+r : r=0..3}
__global__ void __launch_bounds__(256) k_knn(const float* __restrict__ x) {
    int b  = blockIdx.x / (NN / GN);
    int n0 = (blockIdx.x % (NN / GN)) * GN;
    __shared__ float xn[GN][DD];
    __shared__ float dist[GN][NN];
    __shared__ float wvv[8];
    __shared__ int   wii[8];
    __shared__ int   wins;
    int tid = threadIdx.x;
    int wid = tid >> 5, lane = tid & 31;

    const float* xb = x + (size_t)b * DD * NN;
    for (int i = tid; i < GN * DD; i += 256) {
        int g = i / DD, d = i % DD;
        xn[g][d] = xb[(size_t)d * NN + n0 + g];
    }
    __syncthreads();

    float sqn[GN];
#pragma unroll
    for (int g = 0; g < GN; g++) sqn[g] = g_sq[b * NN + n0 + g];

    float dot[GN][8];
#pragma unroll
    for (int g = 0; g < GN; g++)
#pragma unroll
        for (int i = 0; i < 8; i++) dot[g][i] = 0.f;

    for (int d = 0; d < DD; d++) {
        const float4* row4 = (const float4*)(xb + (size_t)d * NN);
        float4 a0 = row4[tid];
        float4 a1 = row4[tid + 256];
        float xv[8] = {a0.x, a0.y, a0.z, a0.w, a1.x, a1.y, a1.z, a1.w};
#pragma unroll
        for (int g = 0; g < GN; g++) {
            float xnv = xn[g][d];
#pragma unroll
            for (int i = 0; i < 8; i++) dot[g][i] = __fmaf_rn(xnv, xv[i], dot[g][i]);
        }
    }
#pragma unroll
    for (int i = 0; i < 8; i++) {
        int m = 4 * tid + (i & 3) + (i >> 2) * 1024;
        float sm = g_sq[b * NN + m];
#pragma unroll
        for (int g = 0; g < GN; g++) {
            float t  = __fadd_rn(sqn[g], sm);
            float u  = __fmul_rn(2.f, dot[g][i]);
            float dv = __fsub_rn(t, u);
            dist[g][m] = (m == n0 + g) ? 1e30f : dv;
        }
    }
    __syncthreads();

    for (int g = 0; g < GN; g++) {
        float bv = 1e30f; int bi = 1 << 29;
#pragma unroll
        for (int i = 0; i < 8; i++) {
            int m = 4 * tid + (i & 3) + (i >> 2) * 1024;
            float v = dist[g][m];
            if (v < bv || (v == bv && m < bi)) { bv = v; bi = m; }
        }
        for (int kk = 0; kk < KK; kk++) {
            float v = bv; int idx = bi;
#pragma unroll
            for (int s = 16; s; s >>= 1) {
                float vo = __shfl_xor_sync(0xffffffffu, v, s);
                int   io = __shfl_xor_sync(0xffffffffu, idx, s);
                if (vo < v || (vo == v && io < idx)) { v = vo; idx = io; }
            }
            if (lane == 0) { wvv[wid] = v; wii[wid] = idx; }
            __syncthreads();
            if (wid == 0) {
                float v2 = (lane < 8) ? wvv[lane] : 1e30f;
                int   i2 = (lane < 8) ? wii[lane] : (1 << 29);
#pragma unroll
                for (int s = 4; s; s >>= 1) {
                    float vo = __shfl_xor_sync(0xffffffffu, v2, s);
                    int   io = __shfl_xor_sync(0xffffffffu, i2, s);
                    if (vo < v2 || (vo == v2 && io < i2)) { v2 = vo; i2 = io; }
                }
                if (lane == 0) {
                    wins = i2;
                    g_idx[(b * NN + n0 + g) * KK + kk] = i2;
                }
            }
            __syncthreads();
            int w = wins;
            if (((w & 1023) >> 2) == tid) {     // owner removes + rescans its 8
                dist[g][w] = 1e30f;
                bv = 1e30f; bi = 1 << 29;
#pragma unroll
                for (int i = 0; i < 8; i++) {
                    int m = 4 * tid + (i & 3) + (i >> 2) * 1024;
                    float vv = dist[g][m];
                    if (vv < bv || (vv == bv && m < bi)) { bv = vv; bi = m; }
                }
            }
        }
    }
}

// ---------------- kernel 3: edge features + conv1 + BN1 partials -------------
// 256 threads, G1=4 points, 2 blocks/SM; sliding-window edge regs (~104 live).
// dyn smem: ee_s[2560][4] (40KB) + w_s[2][2*W1SLAB] (44KB) = 84KB
__global__ void __launch_bounds__(256, 2) k_conv1(const float* __restrict__ x,
                                                  const float* __restrict__ b1) {
    extern __shared__ float smem[];
    float* ee_s = smem;                   // [m = c*20+k][g], stride G1=4
    float* w_s  = smem + CC * KK * G1;    // [2][2*W1SLAB]
    int b  = blockIdx.x / (NN / G1);
    int n0 = (blockIdx.x % (NN / G1)) * G1;
    int tid = threadIdx.x;
    const float* xb = x + (size_t)b * DD * NN;

    for (int i = tid; i < G1 * CC * KK; i += 256) {
        int g = i & 3;
        int m = i >> 2;
        int c = m / KK, k = m % KK;
        int n = n0 + g;
        float v;
        if (c < DD) {
            v = xb[(size_t)c * NN + n];
        } else {
            int mm = g_idx[(b * NN + n) * KK + k];
            int d = c - DD;
            v = xb[(size_t)d * NN + mm] - xb[(size_t)d * NN + n];
        }
        ee_s[i] = v;
        g_ee[(size_t)(b * NN + n) * (CC * KK) + m] = v;
    }
    {
        const float4* src = (const float4*)g_w1t;
        float4* dst = (float4*)w_s;
        for (int i = tid; i < 2 * W1SLAB / 4; i += 256) dst[i] = src[i];
    }
    __syncthreads();

    int o = tid;
    ull acc[2][J1];
#pragma unroll
    for (int p = 0; p < 2; p++)
#pragma unroll
        for (int j = 0; j < J1; j++) acc[p][j] = 0ull;

    for (int cc0 = 0; cc0 < CC; cc0 += 2) {
        int cur = (cc0 >> 1) & 1;
        if (cc0 + 2 < CC) {
            const float4* src = (const float4*)&g_w1t[(cc0 + 2) * W1SLAB];
            float4* dst = (float4*)&w_s[(cur ^ 1) * (2 * W1SLAB)];
            for (int i = tid; i < 2 * W1SLAB / 4; i += 256) dst[i] = src[i];
        }
#pragma unroll
        for (int dc = 0; dc < 2; dc++) {
            int c = cc0 + dc;
            ull wd[T1];
#pragma unroll
            for (int t = 0; t < T1; t++)
                wd[t] = dup2(w_s[cur * (2 * W1SLAB) + dc * W1SLAB + o * T1 + t]);
            const float* ers = &ee_s[c * KK * G1];
#pragma unroll
            for (int p = 0; p < 2; p++) {
                ull wnd[T1];                         // ring: e[k] at slot k%11
#pragma unroll
                for (int t = 0; t < T1; t++)
                    wnd[t] = *(const ull*)&ers[t * G1 + 2 * p];
#pragma unroll
                for (int j = 0; j < J1; j++) {
#pragma unroll
                    for (int t = 0; t < T1; t++)
                        acc[p][j] = fma2(wnd[(j + t) % T1], wd[t], acc[p][j]);
                    if (j < J1 - 1)
                        wnd[j % T1] = *(const ull*)&ers[(j + T1) * G1 + 2 * p];
                }
            }
        }
        __syncthreads();
    }
    float bias = b1[o];
    float s1 = 0.f, s2 = 0.f;
#pragma unroll
    for (int p = 0; p < 2; p++)
#pragma unroll
        for (int j = 0; j < J1; j++) {
            float2 v = unpk(acc[p][j]);
            float vx = v.x + bias, vy = v.y + bias;
            g_h[((size_t)(b * NN + n0 + 2 * p)     * O1 + o) * J1 + j] = vx;
            g_h[((size_t)(b * NN + n0 + 2 * p + 1) * O1 + o) * J1 + j] = vy;
            s1 += vx + vy; s2 += vx * vx + vy * vy;
        }
    g_p1[blockIdx.x * O1 + o] = s1;      // coalesced per-block BN1 partials
    g_p2[blockIdx.x * O1 + o] = s2;
}

// ---------------- kernel 4: BN1 finalize (deterministic) ----------------
__global__ void k_bn1fin(const float* __restrict__ gamma, const float* __restrict__ beta) {
    int o = blockIdx.x;
    int tid = threadIdx.x;
    float s = 0.f, s2 = 0.f;
    for (int blk = tid; blk < NB1; blk += 256) {
        s  += g_p1[blk * O1 + o];
        s2 += g_p2[blk * O1 + o];
    }
    __shared__ float rs[256], rs2[256];
    rs[tid] = s; rs2[tid] = s2;
    __syncthreads();
    for (int t = 128; t > 0; t >>= 1) {
        if (tid < t) { rs[tid] += rs[tid + t]; rs2[tid] += rs2[tid + t]; }
        __syncthreads();
    }
    if (tid == 0) {
        float cnt  = (float)(BB * NN * J1);
        float mean = rs[0] / cnt;
        float var  = rs2[0] / cnt - mean * mean;
        float a    = gamma[o] * rsqrtf(var + 1e-5f);
        g_bn1a[o] = a;
        g_bn1b[o] = beta[o] - mean * a;
    }
}

// ---------------- kernel 5: conv2, c-chunked, batched weight loads ------------
__global__ void __launch_bounds__(256) k_conv2c(const float* __restrict__ b2, int pass) {
    extern __shared__ float smem[];
    float* ee2 = smem;                    // [cl*20+k][g] stride RPAD
    float* hp2 = smem + CCH * KK * RPAD;
    int b  = blockIdx.x / (NN / G2P);
    int n0 = (blockIdx.x % (NN / G2P)) * G2P;
    int c0 = pass * CCH;
    int tid = threadIdx.x;

    for (int i = tid; i < G2P * CCH * KK; i += 256) {
        int g = i / (CCH * KK);
        int m = i % (CCH * KK);
        ee2[m * RPAD + g] = g_ee[(size_t)(b * NN + n0 + g) * (CC * KK) + c0 * KK + m];
    }
    for (int i = tid; i < G2P * CCH * KK; i += 256) {
        int g = i / (CCH * KK);
        int m = i % (CCH * KK);
        int lin = c0 * KK + m;
        int o = lin / J1;
        float raw = g_h[(size_t)(b * NN + n0 + g) * (O1 * J1) + lin];
        float v = g_bn1a[o] * raw + g_bn1b[o];
        hp2[m * RPAD + g] = v > 0.f ? v : 0.01f * v;
    }
    __syncthreads();

    int o2 = tid;
    ull acc[G2P / 2];
#pragma unroll
    for (int p = 0; p < G2P / 2; p++) acc[p] = 0ull;

    for (int cl = 0; cl < CCH; cl++) {
        const float* wrow = &g_w2t[((c0 + cl) * SS) * O2C + o2];
        const float* er = &ee2[cl * KK * RPAD];
        const float* hr = &hp2[cl * KK * RPAD];
#pragma unroll
        for (int sb = 0; sb < KK; sb += 10) {       // er half, batches of 10
            ull wd10[10];
#pragma unroll
            for (int q = 0; q < 10; q++) wd10[q] = dup2(wrow[(sb + q) * O2C]);
#pragma unroll
            for (int q = 0; q < 10; q++) {
                const float* row = &er[(sb + q) * RPAD];
#pragma unroll
                for (int p = 0; p < G2P / 2; p++)
                    acc[p] = fma2(*(const ull*)&row[2 * p], wd10[q], acc[p]);
            }
        }
#pragma unroll
        for (int sb = 0; sb < KK; sb += 10) {       // hr half
            ull wd10[10];
#pragma unroll
            for (int q = 0; q < 10; q++) wd10[q] = dup2(wrow[(KK + sb + q) * O2C]);
#pragma unroll
            for (int q = 0; q < 10; q++) {
                const float* row = &hr[(sb + q) * RPAD];
#pragma unroll
                for (int p = 0; p < G2P / 2; p++)
                    acc[p] = fma2(*(const ull*)&row[2 * p], wd10[q], acc[p]);
            }
        }
    }

    if (pass == 0) {
        float bias = b2[o2];
#pragma unroll
        for (int p = 0; p < G2P / 2; p++) {
            float2 v = unpk(acc[p]);
            g_y[(b * NN + n0 + 2 * p)     * O2C + o2] = v.x + bias;
            g_y[(b * NN + n0 + 2 * p + 1) * O2C + o2] = v.y + bias;
        }
    } else if (pass < NCH - 1) {
#pragma unroll
        for (int p = 0; p < G2P / 2; p++) {
            float2 v = unpk(acc[p]);
            g_y[(b * NN + n0 + 2 * p)     * O2C + o2] += v.x;
            g_y[(b * NN + n0 + 2 * p + 1) * O2C + o2] += v.y;
        }
    } else {                                        // last pass: finalize + BN2 partials
        float s1 = 0.f, s2 = 0.f;
#pragma unroll
        for (int p = 0; p < G2P / 2; p++) {
            float2 v = unpk(acc[p]);
            float yx = g_y[(b * NN + n0 + 2 * p)     * O2C + o2] + v.x;
            float yy = g_y[(b * NN + n0 + 2 * p + 1) * O2C + o2] + v.y;
            g_y[(b * NN + n0 + 2 * p)     * O2C + o2] = yx;
            g_y[(b * NN + n0 + 2 * p + 1) * O2C + o2] = yy;
            s1 += yx + yy; s2 += yx * yx + yy * yy;
        }
        g_q1[blockIdx.x * O2C + o2] = s1;
        g_q2[blockIdx.x * O2C + o2] = s2;
    }
}

// ---------------- kernel 6: BN2 finalize ----------------
__global__ void k_bn2fin(const float* __restrict__ gamma, const float* __restrict__ beta) {
    int o = blockIdx.x;
    int tid = threadIdx.x;
    float s = 0.f, s2 = 0.f;
    for (int blk = tid; blk < NB2; blk += 256) {
        s  += g_q1[blk * O2C + o];
        s2 += g_q2[blk * O2C + o];
    }
    __shared__ float rs[256], rs2[256];
    rs[tid] = s; rs2[tid] = s2;
    __syncthreads();
    for (int t = 128; t > 0; t >>= 1) {
        if (tid < t) { rs[tid] += rs[tid + t]; rs2[tid] += rs2[tid + t]; }
        __syncthreads();
    }
    if (tid == 0) {
        float cnt  = (float)(BB * NN);
        float mean = rs[0] / cnt;
        float var  = rs2[0] / cnt - mean * mean;
        float a    = gamma[o] * rsqrtf(var + 1e-5f);
        g_bn2a[o] = a;
        g_bn2b[o] = beta[o] - mean * a;
    }
}

// ---------------- kernel 7: BN2 apply + relu + reshape ----------------
__global__ void k_out(float* __restrict__ out) {
    int i = blockIdx.x * 256 + threadIdx.x;
    if (i >= BB * 128 * 4096) return;
    int b = i >> 19;
    int r = i & 524287;
    int f = r >> 12;
    int m = r & 4095;
    int o2 = f * 2 + (m >> 11);
    int n  = m & 2047;
    float v = g_bn2a[o2] * g_y[(b * NN + n) * O2C + o2] + g_bn2b[o2];
    out[i] = v > 0.f ? v : 0.f;
}

// ---------------- launch ----------------
extern "C" void kernel_launch(void* const* d_in, const int* in_sizes, int n_in,
                              void* d_out, int out_size) {
    const float* x   = (const float*)d_in[0];
    const float* w1  = (const float*)d_in[1];
    const float* b1  = (const float*)d_in[2];
    const float* g1  = (const float*)d_in[3];
    const float* be1 = (const float*)d_in[4];
    const float* w2  = (const float*)d_in[5];
    const float* b2  = (const float*)d_in[6];
    const float* g2  = (const float*)d_in[7];
    const float* be2 = (const float*)d_in[8];
    float* out = (float*)d_out;

    static int attr_done = 0;
    int smem1 = (CC * KK * G1 + 4 * W1SLAB) * (int)sizeof(float);        // 84KB
    int smem2 = (2 * CCH * KK * RPAD) * (int)sizeof(float);              // 174KB
    if (!attr_done) {
        cudaFuncSetAttribute(k_conv1,  cudaFuncAttributeMaxDynamicSharedMemorySize, smem1);
        cudaFuncSetAttribute(k_conv2c, cudaFuncAttributeMaxDynamicSharedMemorySize, smem2);
        attr_done = 1;
    }

    k_tw1 <<<(CC * O1 * T1 + 255) / 256, 256>>>(w1);
    k_tw2 <<<(CC * SS * O2C + 255) / 256, 256>>>(w2);
    k_sq  <<<(BB * NN + 255) / 256, 256>>>(x);
    k_knn <<<BB * NN / GN, 256>>>(x);
    k_conv1<<<NB1, 256, smem1>>>(x, b1);
    k_bn1fin<<<O1, 256>>>(g1, be1);
    for (int p = 0; p < NCH; p++)
        k_conv2c<<<NB2, 256, smem2>>>(b2, p);
    k_bn2fin<<<O2C, 256>>>(g2, be2);
    k_out <<<(BB * 128 * 4096) / 256, 256>>>(out);
}

// round 9
// speedup vs baseline: 1.9111x; 1.4849x over previous
#include <cuda_runtime.h>
#include <math.h>
#include <stdint.h>

// Problem constants
#define BB   8
#define DD   64      // FIN
#define NN   2048
#define KK   20      // k neighbors
#define CC   128     // 2*FIN edge-feature channels
#define O1   256     // conv1 out channels
#define J1   10      // conv1 output spatial (20-11+1)
#define T1   11      // conv1 kernel width
#define O2C  256     // conv2 out channels
#define SS   40      // conv2 kernel width (full window)
#define GN   4       // points per knn block
#define G1   4       // points per conv1 block
#define G2P  32      // points per conv2 chunk block
#define NCH  4       // conv2 chunk passes
#define RPAD 34      // conv2 smem row stride
#define W1SLAB (O1 * T1)       // 2816 floats per conv1 diff-channel
#define NB1  (BB * NN / G1)    // 4096 conv1 blocks
#define NB2  (BB * NN / G2P)   // 512 conv2 blocks per pass
#define C2HP (32 * KK)         // 640 hp values per conv2 pass (32 channels)
#define C2ED (16 * KK)         // 320 ed values per conv2 pass (16 diff channels)

typedef unsigned long long ull;

__device__ __forceinline__ ull fma2(ull a, ull b, ull c) {
    ull d;
    asm("fma.rn.f32x2 %0, %1, %2, %3;" : "=l"(d) : "l"(a), "l"(b), "l"(c));
    return d;
}
__device__ __forceinline__ ull dup2(float v) {
    ull d; unsigned int u = __float_as_uint(v);
    asm("mov.b64 %0, {%1, %1};" : "=l"(d) : "r"(u));
    return d;
}
__device__ __forceinline__ float2 unpk(ull v) {
    float2 r;
    asm("mov.b64 {%0, %1}, %2;" : "=f"(r.x), "=f"(r.y) : "l"(v));
    return r;
}

// ---------------- scratch (static device globals; no allocs) ----------------
__device__ float g_sq[BB * NN];
__device__ int   g_idx[BB * NN * KK];
__device__ float g_ed[(size_t)BB * NN * 64 * KK];   // diff channels only  ~84MB
__device__ float g_h [(size_t)BB * NN * O1 * J1];   // [b][n][o][j]
__device__ float g_bn1a[O1];
__device__ float g_bn1b[O1];
__device__ float g_y [BB * NN * O2C];
__device__ float g_bn2a[O2C];
__device__ float g_bn2b[O2C];
__device__ float g_w1t[64 * O1 * T1];               // diff ch: [c-64][o][t]
__device__ float g_w1a[64 * O1];                    // const ch: [c][o] = sum_t w1
__device__ float g_w2t[64 * KK * O2C];              // B: [(c-64)*20+s][o2], s<20
__device__ float g_w2c[CC * KK * O2C];              // C: [c*20+k][o2] from s=20+k
__device__ float g_w2a[64 * O2C];                   // A: [c][o2] = sum_{s<20} w2
__device__ float g_p1[NB1 * O1];
__device__ float g_p2[NB1 * O1];
__device__ float g_q1[NB2 * O2C];
__device__ float g_q2[NB2 * O2C];

// ---------------- weight preprocessing ----------------
__global__ void k_tw1(const float* __restrict__ w1) {
    int i = blockIdx.x * 256 + threadIdx.x;         // 256*128*11
    if (i >= O1 * CC * T1) return;
    int o = i / (CC * T1);
    int r = i % (CC * T1);
    int c = r / T1, t = r % T1;
    if (c >= DD) g_w1t[((c - DD) * O1 + o) * T1 + t] = w1[i];
}
__global__ void k_tw1a(const float* __restrict__ w1) {
    int j = blockIdx.x * 256 + threadIdx.x;         // 64*256
    if (j >= DD * O1) return;
    int c = j & 63, o = j >> 6;
    float s = 0.f;
#pragma unroll
    for (int t = 0; t < T1; t++) s += w1[(o * CC + c) * T1 + t];
    g_w1a[c * O1 + o] = s;
}
__global__ void k_tw2(const float* __restrict__ w2) {
    int i = blockIdx.x * 256 + threadIdx.x;         // 256*128*40
    if (i >= O2C * CC * SS) return;
    int o = i / (CC * SS);
    int r = i % (CC * SS);
    int c = r / SS, s = r % SS;
    if (s >= KK)      g_w2c[(c * KK + (s - KK)) * O2C + o] = w2[i];
    else if (c >= DD) g_w2t[((c - DD) * KK + s) * O2C + o] = w2[i];
}
__global__ void k_tw2a(const float* __restrict__ w2) {
    int j = blockIdx.x * 256 + threadIdx.x;         // 64*256
    if (j >= DD * O2C) return;
    int c = j & 63, o = j >> 6;
    float s = 0.f;
#pragma unroll
    for (int t = 0; t < KK; t++) s += w2[(o * CC + c) * SS + t];
    g_w2a[c * O2C + o] = s;
}

// ---------------- kernel 1: squared norms (mul-then-add, matches ref) --------
__global__ void k_sq(const float* __restrict__ x) {
    int i = blockIdx.x * 256 + threadIdx.x;
    if (i >= BB * NN) return;
    int b = i / NN, n = i % NN;
    const float* xb = x + (size_t)b * DD * NN + n;
    float s = 0.f;
#pragma unroll
    for (int d = 0; d < DD; d++) {
        float v = xb[(size_t)d * NN];
        s = __fadd_rn(s, __fmul_rn(v, v));
    }
    g_sq[i] = s;
}

// ---------------- kernel 2: kNN (unchanged from R7 — exact fp32 path) --------
__global__ void __launch_bounds__(256) k_knn(const float* __restrict__ x) {
    int b  = blockIdx.x / (NN / GN);
    int n0 = (blockIdx.x % (NN / GN)) * GN;
    __shared__ float xn[GN][DD];
    __shared__ float dist[GN][NN];
    __shared__ float wvv[8];
    __shared__ int   wii[8];
    __shared__ int   wins;
    int tid = threadIdx.x;
    int wid = tid >> 5, lane = tid & 31;

    const float* xb = x + (size_t)b * DD * NN;
    for (int i = tid; i < GN * DD; i += 256) {
        int g = i / DD, d = i % DD;
        xn[g][d] = xb[(size_t)d * NN + n0 + g];
    }
    __syncthreads();

    float sqn[GN];
#pragma unroll
    for (int g = 0; g < GN; g++) sqn[g] = g_sq[b * NN + n0 + g];

    float dot[GN][8];
#pragma unroll
    for (int g = 0; g < GN; g++)
#pragma unroll
        for (int i = 0; i < 8; i++) dot[g][i] = 0.f;

    for (int d = 0; d < DD; d++) {
        const float4* row4 = (const float4*)(xb + (size_t)d * NN);
        float4 a0 = row4[tid];
        float4 a1 = row4[tid + 256];
        float xv[8] = {a0.x, a0.y, a0.z, a0.w, a1.x, a1.y, a1.z, a1.w};
#pragma unroll
        for (int g = 0; g < GN; g++) {
            float xnv = xn[g][d];
#pragma unroll
            for (int i = 0; i < 8; i++) dot[g][i] = __fmaf_rn(xnv, xv[i], dot[g][i]);
        }
    }
#pragma unroll
    for (int i = 0; i < 8; i++) {
        int m = 4 * tid + (i & 3) + (i >> 2) * 1024;
        float sm = g_sq[b * NN + m];
#pragma unroll
        for (int g = 0; g < GN; g++) {
            float t  = __fadd_rn(sqn[g], sm);
            float u  = __fmul_rn(2.f, dot[g][i]);
            float dv = __fsub_rn(t, u);
            dist[g][m] = (m == n0 + g) ? 1e30f : dv;
        }
    }
    __syncthreads();

    for (int g = 0; g < GN; g++) {
        float bv = 1e30f; int bi = 1 << 29;
#pragma unroll
        for (int i = 0; i < 8; i++) {
            int m = 4 * tid + (i & 3) + (i >> 2) * 1024;
            float v = dist[g][m];
            if (v < bv || (v == bv && m < bi)) { bv = v; bi = m; }
        }
        for (int kk = 0; kk < KK; kk++) {
            float v = bv; int idx = bi;
#pragma unroll
            for (int s = 16; s; s >>= 1) {
                float vo = __shfl_xor_sync(0xffffffffu, v, s);
                int   io = __shfl_xor_sync(0xffffffffu, idx, s);
                if (vo < v || (vo == v && io < idx)) { v = vo; idx = io; }
            }
            if (lane == 0) { wvv[wid] = v; wii[wid] = idx; }
            __syncthreads();
            if (wid == 0) {
                float v2 = (lane < 8) ? wvv[lane] : 1e30f;
                int   i2 = (lane < 8) ? wii[lane] : (1 << 29);
#pragma unroll
                for (int s = 4; s; s >>= 1) {
                    float vo = __shfl_xor_sync(0xffffffffu, v2, s);
                    int   io = __shfl_xor_sync(0xffffffffu, i2, s);
                    if (vo < v2 || (vo == v2 && io < i2)) { v2 = vo; i2 = io; }
                }
                if (lane == 0) {
                    wins = i2;
                    g_idx[(b * NN + n0 + g) * KK + kk] = i2;
                }
            }
            __syncthreads();
            int w = wins;
            if (((w & 1023) >> 2) == tid) {
                dist[g][w] = 1e30f;
                bv = 1e30f; bi = 1 << 29;
#pragma unroll
                for (int i = 0; i < 8; i++) {
                    int m = 4 * tid + (i & 3) + (i >> 2) * 1024;
                    float vv = dist[g][m];
                    if (vv < bv || (vv == bv && m < bi)) { bv = vv; bi = m; }
                }
            }
        }
    }
}

// ---------------- kernel 3: conv1 = const-GEMV + 64-channel conv -------------
// dyn smem: xn_s[64][4] + ed_s[1280][4] + w_s[2][2*2816] = 16640 floats = 65KB
__global__ void __launch_bounds__(256, 2) k_conv1(const float* __restrict__ x,
                                                  const float* __restrict__ b1) {
    extern __shared__ float smem[];
    float* xn_s = smem;                       // [c][g] stride 4, c<64
    float* ed_s = smem + DD * G1;             // [m=(c-64)*20+k][g] stride 4
    float* w_s  = smem + DD * G1 + DD * KK * G1;
    int b  = blockIdx.x / (NN / G1);
    int n0 = (blockIdx.x % (NN / G1)) * G1;
    int tid = threadIdx.x;
    const float* xb = x + (size_t)b * DD * NN;

    for (int i = tid; i < DD * G1; i += 256) {
        int c = i >> 2, g = i & 3;
        xn_s[i] = xb[(size_t)c * NN + n0 + g];
    }
    for (int i = tid; i < DD * KK * G1; i += 256) {
        int g = i & 3, m = i >> 2;
        int d = m / KK, k = m % KK;
        int n = n0 + g;
        int mm = g_idx[(b * NN + n) * KK + k];
        float v = xb[(size_t)d * NN + mm] - xb[(size_t)d * NN + n];
        ed_s[i] = v;
        g_ed[(size_t)(b * NN + n) * (DD * KK) + m] = v;
    }
    {
        const float4* src = (const float4*)g_w1t;
        float4* dst = (float4*)w_s;
        for (int i = tid; i < 2 * W1SLAB / 4; i += 256) dst[i] = src[i];
    }
    __syncthreads();

    int o = tid;
    // Part A: constant channels GEMV (same for all j)
    ull accA[2] = {0ull, 0ull};
    for (int c = 0; c < DD; c += 4) {            // batch 4 weight LDGs for MLP
        float w4[4];
#pragma unroll
        for (int q = 0; q < 4; q++) w4[q] = g_w1a[(c + q) * O1 + o];
#pragma unroll
        for (int q = 0; q < 4; q++) {
            ull wv = dup2(w4[q]);
            accA[0] = fma2(*(const ull*)&xn_s[(c + q) * G1 + 0], wv, accA[0]);
            accA[1] = fma2(*(const ull*)&xn_s[(c + q) * G1 + 2], wv, accA[1]);
        }
    }

    // Part B: diff channels, 11-tap conv, sliding window
    ull acc[2][J1];
#pragma unroll
    for (int p = 0; p < 2; p++)
#pragma unroll
        for (int j = 0; j < J1; j++) acc[p][j] = 0ull;

    for (int cc0 = 0; cc0 < DD; cc0 += 2) {
        int cur = (cc0 >> 1) & 1;
        if (cc0 + 2 < DD) {
            const float4* src = (const float4*)&g_w1t[(cc0 + 2) * W1SLAB];
            float4* dst = (float4*)&w_s[(cur ^ 1) * (2 * W1SLAB)];
            for (int i = tid; i < 2 * W1SLAB / 4; i += 256) dst[i] = src[i];
        }
#pragma unroll
        for (int dc = 0; dc < 2; dc++) {
            int c = cc0 + dc;
            ull wd[T1];
#pragma unroll
            for (int t = 0; t < T1; t++)
                wd[t] = dup2(w_s[cur * (2 * W1SLAB) + dc * W1SLAB + o * T1 + t]);
            const float* ers = &ed_s[c * KK * G1];
#pragma unroll
            for (int p = 0; p < 2; p++) {
                ull wnd[T1];
#pragma unroll
                for (int t = 0; t < T1; t++)
                    wnd[t] = *(const ull*)&ers[t * G1 + 2 * p];
#pragma unroll
                for (int j = 0; j < J1; j++) {
#pragma unroll
                    for (int t = 0; t < T1; t++)
                        acc[p][j] = fma2(wnd[(j + t) % T1], wd[t], acc[p][j]);
                    if (j < J1 - 1)
                        wnd[j % T1] = *(const ull*)&ers[(j + T1) * G1 + 2 * p];
                }
            }
        }
        __syncthreads();
    }
    float bias = b1[o];
    float2 aA0 = unpk(accA[0]), aA1 = unpk(accA[1]);
    float ax[4] = {aA0.x, aA0.y, aA1.x, aA1.y};
    float s1 = 0.f, s2 = 0.f;
#pragma unroll
    for (int p = 0; p < 2; p++)
#pragma unroll
        for (int j = 0; j < J1; j++) {
            float2 v = unpk(acc[p][j]);
            float vx = v.x + ax[2 * p]     + bias;
            float vy = v.y + ax[2 * p + 1] + bias;
            g_h[((size_t)(b * NN + n0 + 2 * p)     * O1 + o) * J1 + j] = vx;
            g_h[((size_t)(b * NN + n0 + 2 * p + 1) * O1 + o) * J1 + j] = vy;
            s1 += vx + vy; s2 += vx * vx + vy * vy;
        }
    g_p1[blockIdx.x * O1 + o] = s1;
    g_p2[blockIdx.x * O1 + o] = s2;
}

// ---------------- kernel 4: BN1 finalize ----------------
__global__ void k_bn1fin(const float* __restrict__ gamma, const float* __restrict__ beta) {
    int o = blockIdx.x;
    int tid = threadIdx.x;
    float s = 0.f, s2 = 0.f;
    for (int blk = tid; blk < NB1; blk += 256) {
        s  += g_p1[blk * O1 + o];
        s2 += g_p2[blk * O1 + o];
    }
    __shared__ float rs[256], rs2[256];
    rs[tid] = s; rs2[tid] = s2;
    __syncthreads();
    for (int t = 128; t > 0; t >>= 1) {
        if (tid < t) { rs[tid] += rs[tid + t]; rs2[tid] += rs2[tid + t]; }
        __syncthreads();
    }
    if (tid == 0) {
        float cnt  = (float)(BB * NN * J1);
        float mean = rs[0] / cnt;
        float var  = rs2[0] / cnt - mean * mean;
        float a    = gamma[o] * rsqrtf(var + 1e-5f);
        g_bn1a[o] = a;
        g_bn1b[o] = beta[o] - mean * a;
    }
}

// ---------------- kernel 5: conv2 = A(GEMV) + B(ed conv) + C(hp conv) --------
// dyn smem: xs[64*32] + ed2[320][34] + hp2[640][34] = 34688 floats = 138.8KB
__global__ void __launch_bounds__(256) k_conv2c(const float* __restrict__ x,
                                                const float* __restrict__ b2, int pass) {
    extern __shared__ float smem[];
    float* xs  = smem;                        // [c][g] stride 32
    float* ed2 = smem + DD * G2P;             // [m][g] stride RPAD
    float* hp2 = smem + DD * G2P + C2ED * RPAD;
    int b  = blockIdx.x / (NN / G2P);
    int n0 = (blockIdx.x % (NN / G2P)) * G2P;
    int tid = threadIdx.x;

    if (pass == 0) {
        const float* xb = x + (size_t)b * DD * NN;
        for (int i = tid; i < DD * G2P; i += 256) {
            int c = i >> 5, g = i & 31;
            xs[i] = xb[(size_t)c * NN + n0 + g];
        }
    }
    for (int i = tid; i < G2P * C2ED; i += 256) {
        int g = i / C2ED, m = i % C2ED;
        ed2[m * RPAD + g] = g_ed[(size_t)(b * NN + n0 + g) * (DD * KK) + pass * C2ED + m];
    }
    for (int i = tid; i < G2P * C2HP; i += 256) {
        int g = i / C2HP, m = i % C2HP;
        int lin = pass * C2HP + m;
        int o = lin / J1;
        float raw = g_h[(size_t)(b * NN + n0 + g) * (O1 * J1) + lin];
        float v = g_bn1a[o] * raw + g_bn1b[o];
        hp2[m * RPAD + g] = v > 0.f ? v : 0.01f * v;
    }
    __syncthreads();

    int o2 = tid;
    ull acc[G2P / 2];
#pragma unroll
    for (int p = 0; p < G2P / 2; p++) acc[p] = 0ull;

    if (pass == 0) {                           // A: constant-channel GEMV
        for (int c = 0; c < DD; c += 8) {
            float w8[8];
#pragma unroll
            for (int q = 0; q < 8; q++) w8[q] = g_w2a[(c + q) * O2C + o2];
#pragma unroll
            for (int q = 0; q < 8; q++) {
                ull wv = dup2(w8[q]);
                const float* xr = &xs[(c + q) * G2P];
#pragma unroll
                for (int p = 0; p < G2P / 2; p++)
                    acc[p] = fma2(*(const ull*)&xr[2 * p], wv, acc[p]);
            }
        }
    }

    // B: diff-channel ee conv (16 channels this pass)
    for (int dcl = 0; dcl < 16; dcl++) {
        const float* wrow = &g_w2t[((pass * 16 + dcl) * KK) * O2C + o2];
        const float* er = &ed2[dcl * KK * RPAD];
#pragma unroll
        for (int sb = 0; sb < KK; sb += 10) {
            ull wd10[10];
#pragma unroll
            for (int q = 0; q < 10; q++) wd10[q] = dup2(wrow[(sb + q) * O2C]);
#pragma unroll
            for (int q = 0; q < 10; q++) {
                const float* row = &er[(sb + q) * RPAD];
#pragma unroll
                for (int p = 0; p < G2P / 2; p++)
                    acc[p] = fma2(*(const ull*)&row[2 * p], wd10[q], acc[p]);
            }
        }
    }
    // C: inte (hp) conv (32 channels this pass)
    for (int cl = 0; cl < 32; cl++) {
        const float* wrow = &g_w2c[((pass * 32 + cl) * KK) * O2C + o2];
        const float* hr = &hp2[cl * KK * RPAD];
#pragma unroll
        for (int sb = 0; sb < KK; sb += 10) {
            ull wd10[10];
#pragma unroll
            for (int q = 0; q < 10; q++) wd10[q] = dup2(wrow[(sb + q) * O2C]);
#pragma unroll
            for (int q = 0; q < 10; q++) {
                const float* row = &hr[(sb + q) * RPAD];
#pragma unroll
                for (int p = 0; p < G2P / 2; p++)
                    acc[p] = fma2(*(const ull*)&row[2 * p], wd10[q], acc[p]);
            }
        }
    }

    if (pass == 0) {
        float bias = b2[o2];
#pragma unroll
        for (int p = 0; p < G2P / 2; p++) {
            float2 v = unpk(acc[p]);
            g_y[(b * NN + n0 + 2 * p)     * O2C + o2] = v.x + bias;
            g_y[(b * NN + n0 + 2 * p + 1) * O2C + o2] = v.y + bias;
        }
    } else if (pass < NCH - 1) {
#pragma unroll
        for (int p = 0; p < G2P / 2; p++) {
            float2 v = unpk(acc[p]);
            g_y[(b * NN + n0 + 2 * p)     * O2C + o2] += v.x;
            g_y[(b * NN + n0 + 2 * p + 1) * O2C + o2] += v.y;
        }
    } else {
        float s1 = 0.f, s2 = 0.f;
#pragma unroll
        for (int p = 0; p < G2P / 2; p++) {
            float2 v = unpk(acc[p]);
            float yx = g_y[(b * NN + n0 + 2 * p)     * O2C + o2] + v.x;
            float yy = g_y[(b * NN + n0 + 2 * p + 1) * O2C + o2] + v.y;
            g_y[(b * NN + n0 + 2 * p)     * O2C + o2] = yx;
            g_y[(b * NN + n0 + 2 * p + 1) * O2C + o2] = yy;
            s1 += yx + yy; s2 += yx * yx + yy * yy;
        }
        g_q1[blockIdx.x * O2C + o2] = s1;
        g_q2[blockIdx.x * O2C + o2] = s2;
    }
}

// ---------------- kernel 6: BN2 finalize ----------------
__global__ void k_bn2fin(const float* __restrict__ gamma, const float* __restrict__ beta) {
    int o = blockIdx.x;
    int tid = threadIdx.x;
    float s = 0.f, s2 = 0.f;
    for (int blk = tid; blk < NB2; blk += 256) {
        s  += g_q1[blk * O2C + o];
        s2 += g_q2[blk * O2C + o];
    }
    __shared__ float rs[256], rs2[256];
    rs[tid] = s; rs2[tid] = s2;
    __syncthreads();
    for (int t = 128; t > 0; t >>= 1) {
        if (tid < t) { rs[tid] += rs[tid + t]; rs2[tid] += rs2[tid + t]; }
        __syncthreads();
    }
    if (tid == 0) {
        float cnt  = (float)(BB * NN);
        float mean = rs[0] / cnt;
        float var  = rs2[0] / cnt - mean * mean;
        float a    = gamma[o] * rsqrtf(var + 1e-5f);
        g_bn2a[o] = a;
        g_bn2b[o] = beta[o] - mean * a;
    }
}

// ---------------- kernel 7: BN2 apply + relu + reshape ----------------
__global__ void k_out(float* __restrict__ out) {
    int i = blockIdx.x * 256 + threadIdx.x;
    if (i >= BB * 128 * 4096) return;
    int b = i >> 19;
    int r = i & 524287;
    int f = r >> 12;
    int m = r & 4095;
    int o2 = f * 2 + (m >> 11);
    int n  = m & 2047;
    float v = g_bn2a[o2] * g_y[(b * NN + n) * O2C + o2] + g_bn2b[o2];
    out[i] = v > 0.f ? v : 0.f;
}

// ---------------- launch ----------------
extern "C" void kernel_launch(void* const* d_in, const int* in_sizes, int n_in,
                              void* d_out, int out_size) {
    const float* x   = (const float*)d_in[0];
    const float* w1  = (const float*)d_in[1];
    const float* b1  = (const float*)d_in[2];
    const float* g1  = (const float*)d_in[3];
    const float* be1 = (const float*)d_in[4];
    const float* w2  = (const float*)d_in[5];
    const float* b2  = (const float*)d_in[6];
    const float* g2  = (const float*)d_in[7];
    const float* be2 = (const float*)d_in[8];
    float* out = (float*)d_out;

    static int attr_done = 0;
    int smem1 = (DD * G1 + DD * KK * G1 + 4 * W1SLAB) * (int)sizeof(float);     // ~65KB
    int smem2 = (DD * G2P + (C2ED + C2HP) * RPAD) * (int)sizeof(float);         // ~139KB
    if (!attr_done) {
        cudaFuncSetAttribute(k_conv1,  cudaFuncAttributeMaxDynamicSharedMemorySize, smem1);
        cudaFuncSetAttribute(k_conv2c, cudaFuncAttributeMaxDynamicSharedMemorySize, smem2);
        attr_done = 1;
    }

    k_tw1 <<<(O1 * CC * T1 + 255) / 256, 256>>>(w1);
    k_tw1a<<<(DD * O1 + 255) / 256, 256>>>(w1);
    k_tw2 <<<(O2C * CC * SS + 255) / 256, 256>>>(w2);
    k_tw2a<<<(DD * O2C + 255) / 256, 256>>>(w2);
    k_sq  <<<(BB * NN + 255) / 256, 256>>>(x);
    k_knn <<<BB * NN / GN, 256>>>(x);
    k_conv1<<<NB1, 256, smem1>>>(x, b1);
    k_bn1fin<<<O1, 256>>>(g1, be1);
    for (int p = 0; p < NCH; p++)
        k_conv2c<<<NB2, 256, smem2>>>(x, b2, p);
    k_bn2fin<<<O2C, 256>>>(g2, be2);
    k_out <<<(BB * 128 * 4096) / 256, 256>>>(out);
}

// round 10
// speedup vs baseline: 2.4514x; 1.2827x over previous
#include <cuda_runtime.h>
#include <math.h>
#include <stdint.h>

// Problem constants
#define BB   8
#define DD   64      // FIN
#define NN   2048
#define KK   20      // k neighbors
#define CC   128     // 2*FIN edge-feature channels
#define O1   256     // conv1 out channels
#define J1   10      // conv1 output spatial (20-11+1)
#define T1   11      // conv1 kernel width
#define O2C  256     // conv2 out channels
#define SS   40      // conv2 kernel width (full window)
#define GN   4       // points per knn block
#define G1   4       // points per conv1 block
#define G2P  16      // points per conv2 chunk block (2 blocks/SM)
#define NCH  4       // conv2 chunk passes
#define RPAD 18      // conv2 smem row stride (g=16 + pad)
#define W1SLAB (O1 * T1)       // 2816 floats per conv1 diff-channel
#define NB1  (BB * NN / G1)    // 4096 conv1 blocks
#define NB2  (BB * NN / G2P)   // 1024 conv2 blocks per pass
#define C2HP (32 * KK)         // 640 hp values per conv2 pass (32 channels)
#define C2ED (16 * KK)         // 320 ed values per conv2 pass (16 diff channels)

typedef unsigned long long ull;

__device__ __forceinline__ ull fma2(ull a, ull b, ull c) {
    ull d;
    asm("fma.rn.f32x2 %0, %1, %2, %3;" : "=l"(d) : "l"(a), "l"(b), "l"(c));
    return d;
}
__device__ __forceinline__ ull dup2(float v) {
    ull d; unsigned int u = __float_as_uint(v);
    asm("mov.b64 %0, {%1, %1};" : "=l"(d) : "r"(u));
    return d;
}
__device__ __forceinline__ float2 unpk(ull v) {
    float2 r;
    asm("mov.b64 {%0, %1}, %2;" : "=f"(r.x), "=f"(r.y) : "l"(v));
    return r;
}

// ---------------- scratch (static device globals; no allocs) ----------------
__device__ float g_sq[BB * NN];
__device__ int   g_idx[BB * NN * KK];
__device__ float g_ed[(size_t)BB * NN * 64 * KK];   // diff channels only  ~84MB
__device__ float g_h [(size_t)BB * NN * J1 * O1];   // [b][n][j][o]  (j-major!)
__device__ float g_bn1a[O1];
__device__ float g_bn1b[O1];
__device__ float g_y [BB * NN * O2C];
__device__ float g_bn2a[O2C];
__device__ float g_bn2b[O2C];
__device__ float g_w1t[64 * O1 * T1];               // diff ch: [c-64][o][t]
__device__ float g_w1a[64 * O1];                    // const ch: [c][o] = sum_t w1
__device__ float g_w2t[64 * KK * O2C];              // B: [(c-64)*20+s][o2], s<20
__device__ float g_w2c[CC * KK * O2C];              // C: [c*20+k][o2] from s=20+k
__device__ float g_w2a[64 * O2C];                   // A: [c][o2] = sum_{s<20} w2
__device__ float g_p1[NB1 * O1];
__device__ float g_p2[NB1 * O1];
__device__ float g_q1[NB2 * O2C];
__device__ float g_q2[NB2 * O2C];

// ---------------- weight preprocessing ----------------
__global__ void k_tw1(const float* __restrict__ w1) {
    int i = blockIdx.x * 256 + threadIdx.x;
    if (i >= O1 * CC * T1) return;
    int o = i / (CC * T1);
    int r = i % (CC * T1);
    int c = r / T1, t = r % T1;
    if (c >= DD) g_w1t[((c - DD) * O1 + o) * T1 + t] = w1[i];
}
__global__ void k_tw1a(const float* __restrict__ w1) {
    int j = blockIdx.x * 256 + threadIdx.x;
    if (j >= DD * O1) return;
    int c = j & 63, o = j >> 6;
    float s = 0.f;
#pragma unroll
    for (int t = 0; t < T1; t++) s += w1[(o * CC + c) * T1 + t];
    g_w1a[c * O1 + o] = s;
}
__global__ void k_tw2(const float* __restrict__ w2) {
    int i = blockIdx.x * 256 + threadIdx.x;
    if (i >= O2C * CC * SS) return;
    int o = i / (CC * SS);
    int r = i % (CC * SS);
    int c = r / SS, s = r % SS;
    if (s >= KK)      g_w2c[(c * KK + (s - KK)) * O2C + o] = w2[i];
    else if (c >= DD) g_w2t[((c - DD) * KK + s) * O2C + o] = w2[i];
}
__global__ void k_tw2a(const float* __restrict__ w2) {
    int j = blockIdx.x * 256 + threadIdx.x;
    if (j >= DD * O2C) return;
    int c = j & 63, o = j >> 6;
    float s = 0.f;
#pragma unroll
    for (int t = 0; t < KK; t++) s += w2[(o * CC + c) * SS + t];
    g_w2a[c * O2C + o] = s;
}

// ---------------- kernel 1: squared norms (mul-then-add, matches ref) --------
__global__ void k_sq(const float* __restrict__ x) {
    int i = blockIdx.x * 256 + threadIdx.x;
    if (i >= BB * NN) return;
    int b = i / NN, n = i % NN;
    const float* xb = x + (size_t)b * DD * NN + n;
    float s = 0.f;
#pragma unroll
    for (int d = 0; d < DD; d++) {
        float v = xb[(size_t)d * NN];
        s = __fadd_rn(s, __fmul_rn(v, v));
    }
    g_sq[i] = s;
}

// ---------------- kernel 2: kNN — group-parallel deterministic top-20 --------
__global__ void __launch_bounds__(256) k_knn(const float* __restrict__ x) {
    int b  = blockIdx.x / (NN / GN);
    int n0 = (blockIdx.x % (NN / GN)) * GN;
    __shared__ float xn[GN][DD];
    __shared__ float dist[GN][NN];
    __shared__ float gwv[GN][2][2];   // [g][round parity][warp-in-group]
    __shared__ int   gwi[GN][2][2];
    int tid = threadIdx.x;

    const float* xb = x + (size_t)b * DD * NN;
    for (int i = tid; i < GN * DD; i += 256) {
        int g = i / DD, d = i % DD;
        xn[g][d] = xb[(size_t)d * NN + n0 + g];
    }
    __syncthreads();

    float sqn[GN];
#pragma unroll
    for (int g = 0; g < GN; g++) sqn[g] = g_sq[b * NN + n0 + g];

    float dot[GN][8];
#pragma unroll
    for (int g = 0; g < GN; g++)
#pragma unroll
        for (int i = 0; i < 8; i++) dot[g][i] = 0.f;

    for (int d = 0; d < DD; d++) {
        const float4* row4 = (const float4*)(xb + (size_t)d * NN);
        float4 a0 = row4[tid];
        float4 a1 = row4[tid + 256];
        float xv[8] = {a0.x, a0.y, a0.z, a0.w, a1.x, a1.y, a1.z, a1.w};
#pragma unroll
        for (int g = 0; g < GN; g++) {
            float xnv = xn[g][d];
#pragma unroll
            for (int i = 0; i < 8; i++) dot[g][i] = __fmaf_rn(xnv, xv[i], dot[g][i]);
        }
    }
#pragma unroll
    for (int i = 0; i < 8; i++) {
        int m = 4 * tid + (i & 3) + (i >> 2) * 1024;
        float sm = g_sq[b * NN + m];
#pragma unroll
        for (int g = 0; g < GN; g++) {
            float t  = __fadd_rn(sqn[g], sm);
            float u  = __fmul_rn(2.f, dot[g][i]);
            float dv = __fsub_rn(t, u);
            dist[g][m] = (m == n0 + g) ? 1e30f : dv;
        }
    }
    __syncthreads();

    // selection: 4 groups of 64 threads, one group per query point
    int grp = tid >> 6;                // which g this thread serves
    int lg  = tid & 63;                // lane within group
    int gwarp = (tid >> 5) & 1;        // warp within group

    float bv = 1e30f; int bi = 1 << 29;
#pragma unroll 8
    for (int r = 0; r < 32; r++) {
        int m = lg + 64 * r;
        float v = dist[grp][m];
        if (v < bv || (v == bv && m < bi)) { bv = v; bi = m; }
    }
    for (int kk = 0; kk < KK; kk++) {
        float v = bv; int idx = bi;
#pragma unroll
        for (int s = 16; s; s >>= 1) {
            float vo = __shfl_xor_sync(0xffffffffu, v, s);
            int   io = __shfl_xor_sync(0xffffffffu, idx, s);
            if (vo < v || (vo == v && io < idx)) { v = vo; idx = io; }
        }
        if ((tid & 31) == 0) { gwv[grp][kk & 1][gwarp] = v; gwi[grp][kk & 1][gwarp] = idx; }
        asm volatile("bar.sync %0, 64;" :: "r"(grp + 1) : "memory");
        float v0 = gwv[grp][kk & 1][0], v1 = gwv[grp][kk & 1][1];
        int   i0 = gwi[grp][kk & 1][0], i1 = gwi[grp][kk & 1][1];
        int w = (v1 < v0 || (v1 == v0 && i1 < i0)) ? i1 : i0;
        if (lg == 0) g_idx[(b * NN + n0 + grp) * KK + kk] = w;
        if ((w & 63) == lg) {           // owner removes winner + rescans its 32
            dist[grp][w] = 1e30f;
            bv = 1e30f; bi = 1 << 29;
#pragma unroll 8
            for (int r = 0; r < 32; r++) {
                int m = lg + 64 * r;
                float vv = dist[grp][m];
                if (vv < bv || (vv == bv && m < bi)) { bv = vv; bi = m; }
            }
        }
    }
}

// ---------------- kernel 3: conv1 = const-GEMV + 64-channel conv -------------
// dyn smem: xn_s[64][4] + ed_s[1280][4] + w_s[2][2*2816] = 16640 floats = 65KB
__global__ void __launch_bounds__(256, 2) k_conv1(const float* __restrict__ x,
                                                  const float* __restrict__ b1) {
    extern __shared__ float smem[];
    float* xn_s = smem;                       // [c][g] stride 4, c<64
    float* ed_s = smem + DD * G1;             // [m=(c-64)*20+k][g] stride 4
    float* w_s  = smem + DD * G1 + DD * KK * G1;
    int b  = blockIdx.x / (NN / G1);
    int n0 = (blockIdx.x % (NN / G1)) * G1;
    int tid = threadIdx.x;
    const float* xb = x + (size_t)b * DD * NN;

    for (int i = tid; i < DD * G1; i += 256) {
        int c = i >> 2, g = i & 3;
        xn_s[i] = xb[(size_t)c * NN + n0 + g];
    }
    for (int i = tid; i < DD * KK * G1; i += 256) {
        int g = i & 3, m = i >> 2;
        int d = m / KK, k = m % KK;
        int n = n0 + g;
        int mm = g_idx[(b * NN + n) * KK + k];
        float v = xb[(size_t)d * NN + mm] - xb[(size_t)d * NN + n];
        ed_s[i] = v;
        g_ed[(size_t)(b * NN + n) * (DD * KK) + m] = v;
    }
    {
        const float4* src = (const float4*)g_w1t;
        float4* dst = (float4*)w_s;
        for (int i = tid; i < 2 * W1SLAB / 4; i += 256) dst[i] = src[i];
    }
    __syncthreads();

    int o = tid;
    ull accA[2] = {0ull, 0ull};
    for (int c = 0; c < DD; c += 4) {
        float w4[4];
#pragma unroll
        for (int q = 0; q < 4; q++) w4[q] = g_w1a[(c + q) * O1 + o];
#pragma unroll
        for (int q = 0; q < 4; q++) {
            ull wv = dup2(w4[q]);
            accA[0] = fma2(*(const ull*)&xn_s[(c + q) * G1 + 0], wv, accA[0]);
            accA[1] = fma2(*(const ull*)&xn_s[(c + q) * G1 + 2], wv, accA[1]);
        }
    }

    ull acc[2][J1];
#pragma unroll
    for (int p = 0; p < 2; p++)
#pragma unroll
        for (int j = 0; j < J1; j++) acc[p][j] = 0ull;

    for (int cc0 = 0; cc0 < DD; cc0 += 2) {
        int cur = (cc0 >> 1) & 1;
        if (cc0 + 2 < DD) {
            const float4* src = (const float4*)&g_w1t[(cc0 + 2) * W1SLAB];
            float4* dst = (float4*)&w_s[(cur ^ 1) * (2 * W1SLAB)];
            for (int i = tid; i < 2 * W1SLAB / 4; i += 256) dst[i] = src[i];
        }
#pragma unroll
        for (int dc = 0; dc < 2; dc++) {
            int c = cc0 + dc;
            ull wd[T1];
#pragma unroll
            for (int t = 0; t < T1; t++)
                wd[t] = dup2(w_s[cur * (2 * W1SLAB) + dc * W1SLAB + o * T1 + t]);
            const float* ers = &ed_s[c * KK * G1];
#pragma unroll
            for (int p = 0; p < 2; p++) {
                ull wnd[T1];
#pragma unroll
                for (int t = 0; t < T1; t++)
                    wnd[t] = *(const ull*)&ers[t * G1 + 2 * p];
#pragma unroll
                for (int j = 0; j < J1; j++) {
#pragma unroll
                    for (int t = 0; t < T1; t++)
                        acc[p][j] = fma2(wnd[(j + t) % T1], wd[t], acc[p][j]);
                    if (j < J1 - 1)
                        wnd[j % T1] = *(const ull*)&ers[(j + T1) * G1 + 2 * p];
                }
            }
        }
        __syncthreads();
    }
    float bias = b1[o];
    float2 aA0 = unpk(accA[0]), aA1 = unpk(accA[1]);
    float ax[4] = {aA0.x, aA0.y, aA1.x, aA1.y};
    float s1 = 0.f, s2 = 0.f;
#pragma unroll
    for (int p = 0; p < 2; p++)
#pragma unroll
        for (int j = 0; j < J1; j++) {
            float2 v = unpk(acc[p][j]);
            float vx = v.x + ax[2 * p]     + bias;
            float vy = v.y + ax[2 * p + 1] + bias;
            // j-major layout: coalesced across o
            g_h[((size_t)(b * NN + n0 + 2 * p)     * J1 + j) * O1 + o] = vx;
            g_h[((size_t)(b * NN + n0 + 2 * p + 1) * J1 + j) * O1 + o] = vy;
            s1 += vx + vy; s2 += vx * vx + vy * vy;
        }
    g_p1[blockIdx.x * O1 + o] = s1;
    g_p2[blockIdx.x * O1 + o] = s2;
}

// ---------------- kernel 4: BN1 finalize ----------------
__global__ void k_bn1fin(const float* __restrict__ gamma, const float* __restrict__ beta) {
    int o = blockIdx.x;
    int tid = threadIdx.x;
    float s = 0.f, s2 = 0.f;
    for (int blk = tid; blk < NB1; blk += 256) {
        s  += g_p1[blk * O1 + o];
        s2 += g_p2[blk * O1 + o];
    }
    __shared__ float rs[256], rs2[256];
    rs[tid] = s; rs2[tid] = s2;
    __syncthreads();
    for (int t = 128; t > 0; t >>= 1) {
        if (tid < t) { rs[tid] += rs[tid + t]; rs2[tid] += rs2[tid + t]; }
        __syncthreads();
    }
    if (tid == 0) {
        float cnt  = (float)(BB * NN * J1);
        float mean = rs[0] / cnt;
        float var  = rs2[0] / cnt - mean * mean;
        float a    = gamma[o] * rsqrtf(var + 1e-5f);
        g_bn1a[o] = a;
        g_bn1b[o] = beta[o] - mean * a;
    }
}

// ---------------- kernel 5: conv2 = A(GEMV) + B(ed conv) + C(hp conv) --------
// G2P=16: smem = xs[64*16] + ed2[320*18] + hp2[640*18] = 18304 floats = 73KB
__global__ void __launch_bounds__(256, 2) k_conv2c(const float* __restrict__ x,
                                                   const float* __restrict__ b2, int pass) {
    extern __shared__ float smem[];
    float* xs  = smem;                        // [c][g] stride 16
    float* ed2 = smem + DD * G2P;             // [m][g] stride RPAD
    float* hp2 = smem + DD * G2P + C2ED * RPAD;
    int b  = blockIdx.x / (NN / G2P);
    int n0 = (blockIdx.x % (NN / G2P)) * G2P;
    int tid = threadIdx.x;

    if (pass == 0) {
        const float* xb = x + (size_t)b * DD * NN;
        for (int i = tid; i < DD * G2P; i += 256) {
            int c = i >> 4, g = i & 15;
            xs[i] = xb[(size_t)c * NN + n0 + g];
        }
    }
    for (int i = tid; i < G2P * C2ED; i += 256) {
        int g = i / C2ED, m = i % C2ED;
        ed2[m * RPAD + g] = g_ed[(size_t)(b * NN + n0 + g) * (DD * KK) + pass * C2ED + m];
    }
    // hp staging: gmem reads (j,o)-major (coalesced over o), scattered STS
    for (int i = tid; i < G2P * C2HP; i += 256) {
        int g = i / C2HP, r = i % C2HP;
        int j = r >> 6, oo = r & 63;          // o = pass*64 + oo
        int o = pass * 64 + oo;
        float raw = g_h[((size_t)(b * NN + n0 + g) * J1 + j) * O1 + o];
        float v = g_bn1a[o] * raw + g_bn1b[o];
        v = v > 0.f ? v : 0.01f * v;
        int cl = oo >> 1;                     // channel within pass chunk
        int k  = (oo & 1) * J1 + j;           // tap index
        hp2[(cl * KK + k) * RPAD + g] = v;
    }
    __syncthreads();

    int o2 = tid;
    ull acc[G2P / 2];
#pragma unroll
    for (int p = 0; p < G2P / 2; p++) acc[p] = 0ull;

    if (pass == 0) {                           // A: constant-channel GEMV
        for (int c = 0; c < DD; c += 8) {
            float w8[8];
#pragma unroll
            for (int q = 0; q < 8; q++) w8[q] = g_w2a[(c + q) * O2C + o2];
#pragma unroll
            for (int q = 0; q < 8; q++) {
                ull wv = dup2(w8[q]);
                const float* xr = &xs[(c + q) * G2P];
#pragma unroll
                for (int p = 0; p < G2P / 2; p++)
                    acc[p] = fma2(*(const ull*)&xr[2 * p], wv, acc[p]);
            }
        }
    }

    // B: diff-channel ee conv (16 channels this pass)
    for (int dcl = 0; dcl < 16; dcl++) {
        const float* wrow = &g_w2t[((pass * 16 + dcl) * KK) * O2C + o2];
        const float* er = &ed2[dcl * KK * RPAD];
#pragma unroll
        for (int sb = 0; sb < KK; sb += 10) {
            ull wd10[10];
#pragma unroll
            for (int q = 0; q < 10; q++) wd10[q] = dup2(wrow[(sb + q) * O2C]);
#pragma unroll
            for (int q = 0; q < 10; q++) {
                const float* row = &er[(sb + q) * RPAD];
#pragma unroll
                for (int p = 0; p < G2P / 2; p++)
                    acc[p] = fma2(*(const ull*)&row[2 * p], wd10[q], acc[p]);
            }
        }
    }
    // C: inte (hp) conv (32 channels this pass)
    for (int cl = 0; cl < 32; cl++) {
        const float* wrow = &g_w2c[((pass * 32 + cl) * KK) * O2C + o2];
        const float* hr = &hp2[cl * KK * RPAD];
#pragma unroll
        for (int sb = 0; sb < KK; sb += 10) {
            ull wd10[10];
#pragma unroll
            for (int q = 0; q < 10; q++) wd10[q] = dup2(wrow[(sb + q) * O2C]);
#pragma unroll
            for (int q = 0; q < 10; q++) {
                const float* row = &hr[(sb + q) * RPAD];
#pragma unroll
                for (int p = 0; p < G2P / 2; p++)
                    acc[p] = fma2(*(const ull*)&row[2 * p], wd10[q], acc[p]);
            }
        }
    }

    if (pass == 0) {
        float bias = b2[o2];
#pragma unroll
        for (int p = 0; p < G2P / 2; p++) {
            float2 v = unpk(acc[p]);
            g_y[(b * NN + n0 + 2 * p)     * O2C + o2] = v.x + bias;
            g_y[(b * NN + n0 + 2 * p + 1) * O2C + o2] = v.y + bias;
        }
    } else if (pass < NCH - 1) {
#pragma unroll
        for (int p = 0; p < G2P / 2; p++) {
            float2 v = unpk(acc[p]);
            g_y[(b * NN + n0 + 2 * p)     * O2C + o2] += v.x;
            g_y[(b * NN + n0 + 2 * p + 1) * O2C + o2] += v.y;
        }
    } else {
        float s1 = 0.f, s2 = 0.f;
#pragma unroll
        for (int p = 0; p < G2P / 2; p++) {
            float2 v = unpk(acc[p]);
            float yx = g_y[(b * NN + n0 + 2 * p)     * O2C + o2] + v.x;
            float yy = g_y[(b * NN + n0 + 2 * p + 1) * O2C + o2] + v.y;
            g_y[(b * NN + n0 + 2 * p)     * O2C + o2] = yx;
            g_y[(b * NN + n0 + 2 * p + 1) * O2C + o2] = yy;
            s1 += yx + yy; s2 += yx * yx + yy * yy;
        }
        g_q1[blockIdx.x * O2C + o2] = s1;
        g_q2[blockIdx.x * O2C + o2] = s2;
    }
}

// ---------------- kernel 6: BN2 finalize ----------------
__global__ void k_bn2fin(const float* __restrict__ gamma, const float* __restrict__ beta) {
    int o = blockIdx.x;
    int tid = threadIdx.x;
    float s = 0.f, s2 = 0.f;
    for (int blk = tid; blk < NB2; blk += 256) {
        s  += g_q1[blk * O2C + o];
        s2 += g_q2[blk * O2C + o];
    }
    __shared__ float rs[256], rs2[256];
    rs[tid] = s; rs2[tid] = s2;
    __syncthreads();
    for (int t = 128; t > 0; t >>= 1) {
        if (tid < t) { rs[tid] += rs[tid + t]; rs2[tid] += rs2[tid + t]; }
        __syncthreads();
    }
    if (tid == 0) {
        float cnt  = (float)(BB * NN);
        float mean = rs[0] / cnt;
        float var  = rs2[0] / cnt - mean * mean;
        float a    = gamma[o] * rsqrtf(var + 1e-5f);
        g_bn2a[o] = a;
        g_bn2b[o] = beta[o] - mean * a;
    }
}

// ---------------- kernel 7: BN2 apply + relu + reshape ----------------
__global__ void k_out(float* __restrict__ out) {
    int i = blockIdx.x * 256 + threadIdx.x;
    if (i >= BB * 128 * 4096) return;
    int b = i >> 19;
    int r = i & 524287;
    int f = r >> 12;
    int m = r & 4095;
    int o2 = f * 2 + (m >> 11);
    int n  = m & 2047;
    float v = g_bn2a[o2] * g_y[(b * NN + n) * O2C + o2] + g_bn2b[o2];
    out[i] = v > 0.f ? v : 0.f;
}

// ---------------- launch ----------------
extern "C" void kernel_launch(void* const* d_in, const int* in_sizes, int n_in,
                              void* d_out, int out_size) {
    const float* x   = (const float*)d_in[0];
    const float* w1  = (const float*)d_in[1];
    const float* b1  = (const float*)d_in[2];
    const float* g1  = (const float*)d_in[3];
    const float* be1 = (const float*)d_in[4];
    const float* w2  = (const float*)d_in[5];
    const float* b2  = (const float*)d_in[6];
    const float* g2  = (const float*)d_in[7];
    const float* be2 = (const float*)d_in[8];
    float* out = (float*)d_out;

    static int attr_done = 0;
    int smem1 = (DD * G1 + DD * KK * G1 + 4 * W1SLAB) * (int)sizeof(float);      // ~65KB
    int smem2 = (DD * G2P + (C2ED + C2HP) * RPAD) * (int)sizeof(float);          // ~73KB
    if (!attr_done) {
        cudaFuncSetAttribute(k_conv1,  cudaFuncAttributeMaxDynamicSharedMemorySize, smem1);
        cudaFuncSetAttribute(k_conv2c, cudaFuncAttributeMaxDynamicSharedMemorySize, smem2);
        attr_done = 1;
    }

    k_tw1 <<<(O1 * CC * T1 + 255) / 256, 256>>>(w1);
    k_tw1a<<<(DD * O1 + 255) / 256, 256>>>(w1);
    k_tw2 <<<(O2C * CC * SS + 255) / 256, 256>>>(w2);
    k_tw2a<<<(DD * O2C + 255) / 256, 256>>>(w2);
    k_sq  <<<(BB * NN + 255) / 256, 256>>>(x);
    k_knn <<<BB * NN / GN, 256>>>(x);
    k_conv1<<<NB1, 256, smem1>>>(x, b1);
    k_bn1fin<<<O1, 256>>>(g1, be1);
    for (int p = 0; p < NCH; p++)
        k_conv2c<<<NB2, 256, smem2>>>(x, b2, p);
    k_bn2fin<<<O2C, 256>>>(g2, be2);
    k_out <<<(BB * 128 * 4096) / 256, 256>>>(out);
}

// round 11
// speedup vs baseline: 2.5963x; 1.0591x over previous
#include <cuda_runtime.h>
#include <math.h>
#include <stdint.h>

// Problem constants
#define BB   8
#define DD   64      // FIN
#define NN   2048
#define KK   20      // k neighbors
#define CC   128     // 2*FIN edge-feature channels
#define O1   256     // conv1 out channels
#define J1   10      // conv1 output spatial
#define T1   11      // conv1 kernel width
#define O2C  256     // conv2 out channels
#define SS   40      // conv2 kernel width
#define GN   4       // points per knn block
#define G1   4       // points per conv1 block
#define G2P  16      // points per conv2 block
#define NCH  4       // conv2 chunk passes (now internal loop)
#define RPAD 18      // conv2 smem row stride
#define W1SLAB (O1 * T1)       // 2816 floats per conv1 diff-channel
#define NB1  (BB * NN / G1)    // 4096 conv1 blocks
#define NB2  (BB * NN / G2P)   // 1024 conv2 blocks
#define C2HP (32 * KK)         // 640 hp values per conv2 pass
#define C2ED (16 * KK)         // 320 ed values per conv2 pass

typedef unsigned long long ull;

__device__ __forceinline__ ull fma2(ull a, ull b, ull c) {
    ull d;
    asm("fma.rn.f32x2 %0, %1, %2, %3;" : "=l"(d) : "l"(a), "l"(b), "l"(c));
    return d;
}
__device__ __forceinline__ ull dup2(float v) {
    ull d; unsigned int u = __float_as_uint(v);
    asm("mov.b64 %0, {%1, %1};" : "=l"(d) : "r"(u));
    return d;
}
__device__ __forceinline__ float2 unpk(ull v) {
    float2 r;
    asm("mov.b64 {%0, %1}, %2;" : "=f"(r.x), "=f"(r.y) : "l"(v));
    return r;
}

// ---------------- scratch ----------------
__device__ float g_sq[BB * NN];
__device__ int   g_idx[BB * NN * KK];
__device__ float g_ed[(size_t)BB * NN * 64 * KK];
__device__ float g_h [(size_t)BB * NN * J1 * O1];   // [b][n][j][o]
__device__ float g_bn1a[O1];
__device__ float g_bn1b[O1];
__device__ float g_y [BB * NN * O2C];
__device__ float g_bn2a[O2C];
__device__ float g_bn2b[O2C];
__device__ float g_w1t[64 * O1 * T1];
__device__ float g_w1a[64 * O1];
__device__ float g_w2t[64 * KK * O2C];
__device__ float g_w2c[CC * KK * O2C];
__device__ float g_w2a[64 * O2C];
__device__ float g_p1[NB1 * O1];
__device__ float g_p2[NB1 * O1];
__device__ float g_q1[NB2 * O2C];
__device__ float g_q2[NB2 * O2C];

// ---------------- weight preprocessing (merged) ----------------
__global__ void k_tw1x(const float* __restrict__ w1) {
    int i = blockIdx.x * 256 + threadIdx.x;
    if (i < O1 * CC * T1) {
        int o = i / (CC * T1);
        int r = i % (CC * T1);
        int c = r / T1, t = r % T1;
        if (c >= DD) g_w1t[((c - DD) * O1 + o) * T1 + t] = w1[i];
    }
    if (i < DD * O1) {
        int c = i & 63, o = i >> 6;
        float s = 0.f;
#pragma unroll
        for (int t = 0; t < T1; t++) s += w1[(o * CC + c) * T1 + t];
        g_w1a[c * O1 + o] = s;
    }
}
__global__ void k_tw2x(const float* __restrict__ w2) {
    int i = blockIdx.x * 256 + threadIdx.x;
    if (i < O2C * CC * SS) {
        int o = i / (CC * SS);
        int r = i % (CC * SS);
        int c = r / SS, s = r % SS;
        if (s >= KK)      g_w2c[(c * KK + (s - KK)) * O2C + o] = w2[i];
        else if (c >= DD) g_w2t[((c - DD) * KK + s) * O2C + o] = w2[i];
    }
    if (i < DD * O2C) {
        int c = i & 63, o = i >> 6;
        float s = 0.f;
#pragma unroll
        for (int t = 0; t < KK; t++) s += w2[(o * CC + c) * SS + t];
        g_w2a[c * O2C + o] = s;
    }
}

// ---------------- kernel: squared norms (mul-then-add, matches ref) ----------
__global__ void k_sq(const float* __restrict__ x) {
    int i = blockIdx.x * 256 + threadIdx.x;
    if (i >= BB * NN) return;
    int b = i / NN, n = i % NN;
    const float* xb = x + (size_t)b * DD * NN + n;
    float s = 0.f;
#pragma unroll
    for (int d = 0; d < DD; d++) {
        float v = xb[(size_t)d * NN];
        s = __fadd_rn(s, __fmul_rn(v, v));
    }
    g_sq[i] = s;
}

// ---------------- kNN — group-parallel deterministic top-20 ----------
__global__ void __launch_bounds__(256) k_knn(const float* __restrict__ x) {
    int b  = blockIdx.x / (NN / GN);
    int n0 = (blockIdx.x % (NN / GN)) * GN;
    __shared__ float xn[GN][DD];
    __shared__ float dist[GN][NN];
    __shared__ float gwv[GN][2][2];
    __shared__ int   gwi[GN][2][2];
    int tid = threadIdx.x;

    const float* xb = x + (size_t)b * DD * NN;
    for (int i = tid; i < GN * DD; i += 256) {
        int g = i / DD, d = i % DD;
        xn[g][d] = xb[(size_t)d * NN + n0 + g];
    }
    __syncthreads();

    float sqn[GN];
#pragma unroll
    for (int g = 0; g < GN; g++) sqn[g] = g_sq[b * NN + n0 + g];

    float dot[GN][8];
#pragma unroll
    for (int g = 0; g < GN; g++)
#pragma unroll
        for (int i = 0; i < 8; i++) dot[g][i] = 0.f;

    for (int d = 0; d < DD; d++) {
        const float4* row4 = (const float4*)(xb + (size_t)d * NN);
        float4 a0 = row4[tid];
        float4 a1 = row4[tid + 256];
        float xv[8] = {a0.x, a0.y, a0.z, a0.w, a1.x, a1.y, a1.z, a1.w};
#pragma unroll
        for (int g = 0; g < GN; g++) {
            float xnv = xn[g][d];
#pragma unroll
            for (int i = 0; i < 8; i++) dot[g][i] = __fmaf_rn(xnv, xv[i], dot[g][i]);
        }
    }
#pragma unroll
    for (int i = 0; i < 8; i++) {
        int m = 4 * tid + (i & 3) + (i >> 2) * 1024;
        float sm = g_sq[b * NN + m];
#pragma unroll
        for (int g = 0; g < GN; g++) {
            float t  = __fadd_rn(sqn[g], sm);
            float u  = __fmul_rn(2.f, dot[g][i]);
            float dv = __fsub_rn(t, u);
            dist[g][m] = (m == n0 + g) ? 1e30f : dv;
        }
    }
    __syncthreads();

    int grp = tid >> 6;
    int lg  = tid & 63;
    int gwarp = (tid >> 5) & 1;

    float bv = 1e30f; int bi = 1 << 29;
#pragma unroll 8
    for (int r = 0; r < 32; r++) {
        int m = lg + 64 * r;
        float v = dist[grp][m];
        if (v < bv || (v == bv && m < bi)) { bv = v; bi = m; }
    }
    for (int kk = 0; kk < KK; kk++) {
        float v = bv; int idx = bi;
#pragma unroll
        for (int s = 16; s; s >>= 1) {
            float vo = __shfl_xor_sync(0xffffffffu, v, s);
            int   io = __shfl_xor_sync(0xffffffffu, idx, s);
            if (vo < v || (vo == v && io < idx)) { v = vo; idx = io; }
        }
        if ((tid & 31) == 0) { gwv[grp][kk & 1][gwarp] = v; gwi[grp][kk & 1][gwarp] = idx; }
        asm volatile("bar.sync %0, 64;" :: "r"(grp + 1) : "memory");
        float v0 = gwv[grp][kk & 1][0], v1 = gwv[grp][kk & 1][1];
        int   i0 = gwi[grp][kk & 1][0], i1 = gwi[grp][kk & 1][1];
        int w = (v1 < v0 || (v1 == v0 && i1 < i0)) ? i1 : i0;
        if (lg == 0) g_idx[(b * NN + n0 + grp) * KK + kk] = w;
        if ((w & 63) == lg) {
            dist[grp][w] = 1e30f;
            bv = 1e30f; bi = 1 << 29;
#pragma unroll 8
            for (int r = 0; r < 32; r++) {
                int m = lg + 64 * r;
                float vv = dist[grp][m];
                if (vv < bv || (vv == bv && m < bi)) { bv = vv; bi = m; }
            }
        }
    }
}

// ---------------- conv1 = const-GEMV + 64-channel conv, 4-slab staging -------
// dyn smem: xn_s[256] + ed_s[5120] + w_s[2][4*2816] = 27904 floats = 111.6KB
__global__ void __launch_bounds__(256, 2) k_conv1(const float* __restrict__ x,
                                                  const float* __restrict__ b1) {
    extern __shared__ float smem[];
    float* xn_s = smem;
    float* ed_s = smem + DD * G1;
    float* w_s  = smem + DD * G1 + DD * KK * G1;
    int b  = blockIdx.x / (NN / G1);
    int n0 = (blockIdx.x % (NN / G1)) * G1;
    int tid = threadIdx.x;
    const float* xb = x + (size_t)b * DD * NN;

    for (int i = tid; i < DD * G1; i += 256) {
        int c = i >> 2, g = i & 3;
        xn_s[i] = xb[(size_t)c * NN + n0 + g];
    }
    for (int i = tid; i < DD * KK * G1; i += 256) {
        int g = i & 3, m = i >> 2;
        int d = m / KK, k = m % KK;
        int n = n0 + g;
        int mm = g_idx[(b * NN + n) * KK + k];
        float v = xb[(size_t)d * NN + mm] - xb[(size_t)d * NN + n];
        ed_s[i] = v;
        g_ed[(size_t)(b * NN + n) * (DD * KK) + m] = v;
    }
    {
        const float4* src = (const float4*)g_w1t;
        float4* dst = (float4*)w_s;
        for (int i = tid; i < 4 * W1SLAB / 4; i += 256) dst[i] = src[i];
    }
    __syncthreads();

    int o = tid;
    ull accA[2] = {0ull, 0ull};
    for (int c = 0; c < DD; c += 4) {
        float w4[4];
#pragma unroll
        for (int q = 0; q < 4; q++) w4[q] = g_w1a[(c + q) * O1 + o];
#pragma unroll
        for (int q = 0; q < 4; q++) {
            ull wv = dup2(w4[q]);
            accA[0] = fma2(*(const ull*)&xn_s[(c + q) * G1 + 0], wv, accA[0]);
            accA[1] = fma2(*(const ull*)&xn_s[(c + q) * G1 + 2], wv, accA[1]);
        }
    }

    ull acc[2][J1];
#pragma unroll
    for (int p = 0; p < 2; p++)
#pragma unroll
        for (int j = 0; j < J1; j++) acc[p][j] = 0ull;

    for (int cc0 = 0; cc0 < DD; cc0 += 4) {
        int cur = (cc0 >> 2) & 1;
        if (cc0 + 4 < DD) {
            const float4* src = (const float4*)&g_w1t[(cc0 + 4) * W1SLAB];
            float4* dst = (float4*)&w_s[(cur ^ 1) * (4 * W1SLAB)];
            for (int i = tid; i < 4 * W1SLAB / 4; i += 256) dst[i] = src[i];
        }
#pragma unroll
        for (int dc = 0; dc < 4; dc++) {
            int c = cc0 + dc;
            ull wd[T1];
#pragma unroll
            for (int t = 0; t < T1; t++)
                wd[t] = dup2(w_s[cur * (4 * W1SLAB) + dc * W1SLAB + o * T1 + t]);
            const float* ers = &ed_s[c * KK * G1];
#pragma unroll
            for (int p = 0; p < 2; p++) {
                ull wnd[T1];
#pragma unroll
                for (int t = 0; t < T1; t++)
                    wnd[t] = *(const ull*)&ers[t * G1 + 2 * p];
#pragma unroll
                for (int j = 0; j < J1; j++) {
#pragma unroll
                    for (int t = 0; t < T1; t++)
                        acc[p][j] = fma2(wnd[(j + t) % T1], wd[t], acc[p][j]);
                    if (j < J1 - 1)
                        wnd[j % T1] = *(const ull*)&ers[(j + T1) * G1 + 2 * p];
                }
            }
        }
        __syncthreads();
    }
    float bias = b1[o];
    float2 aA0 = unpk(accA[0]), aA1 = unpk(accA[1]);
    float ax[4] = {aA0.x, aA0.y, aA1.x, aA1.y};
    float s1 = 0.f, s2 = 0.f;
#pragma unroll
    for (int p = 0; p < 2; p++)
#pragma unroll
        for (int j = 0; j < J1; j++) {
            float2 v = unpk(acc[p][j]);
            float vx = v.x + ax[2 * p]     + bias;
            float vy = v.y + ax[2 * p + 1] + bias;
            g_h[((size_t)(b * NN + n0 + 2 * p)     * J1 + j) * O1 + o] = vx;
            g_h[((size_t)(b * NN + n0 + 2 * p + 1) * J1 + j) * O1 + o] = vy;
            s1 += vx + vy; s2 += vx * vx + vy * vy;
        }
    g_p1[blockIdx.x * O1 + o] = s1;
    g_p2[blockIdx.x * O1 + o] = s2;
}

// ---------------- BN1 finalize ----------------
__global__ void k_bn1fin(const float* __restrict__ gamma, const float* __restrict__ beta) {
    int o = blockIdx.x;
    int tid = threadIdx.x;
    float s = 0.f, s2 = 0.f;
    for (int blk = tid; blk < NB1; blk += 256) {
        s  += g_p1[blk * O1 + o];
        s2 += g_p2[blk * O1 + o];
    }
    __shared__ float rs[256], rs2[256];
    rs[tid] = s; rs2[tid] = s2;
    __syncthreads();
    for (int t = 128; t > 0; t >>= 1) {
        if (tid < t) { rs[tid] += rs[tid + t]; rs2[tid] += rs2[tid + t]; }
        __syncthreads();
    }
    if (tid == 0) {
        float cnt  = (float)(BB * NN * J1);
        float mean = rs[0] / cnt;
        float var  = rs2[0] / cnt - mean * mean;
        float a    = gamma[o] * rsqrtf(var + 1e-5f);
        g_bn1a[o] = a;
        g_bn1b[o] = beta[o] - mean * a;
    }
}

// ---------------- conv2 fused: all 4 passes, acc in regs ----------------
// smem = xs[64*16] + ed2[320*18] + hp2[640*18] = 18304 floats = 73KB
__global__ void __launch_bounds__(256, 2) k_conv2(const float* __restrict__ x,
                                                  const float* __restrict__ b2) {
    extern __shared__ float smem[];
    float* xs  = smem;
    float* ed2 = smem + DD * G2P;
    float* hp2 = smem + DD * G2P + C2ED * RPAD;
    int b  = blockIdx.x / (NN / G2P);
    int n0 = (blockIdx.x % (NN / G2P)) * G2P;
    int tid = threadIdx.x;
    int o2 = tid;

    {
        const float* xb = x + (size_t)b * DD * NN;
        for (int i = tid; i < DD * G2P; i += 256) {
            int c = i >> 4, g = i & 15;
            xs[i] = xb[(size_t)c * NN + n0 + g];
        }
    }

    ull acc[G2P / 2];
#pragma unroll
    for (int p = 0; p < G2P / 2; p++) acc[p] = 0ull;

    for (int pass = 0; pass < NCH; pass++) {
        if (pass > 0) __syncthreads();          // previous compute done
        for (int i = tid; i < G2P * C2ED; i += 256) {
            int g = i / C2ED, m = i % C2ED;
            ed2[m * RPAD + g] = g_ed[(size_t)(b * NN + n0 + g) * (DD * KK) + pass * C2ED + m];
        }
        for (int i = tid; i < G2P * C2HP; i += 256) {
            int g = i / C2HP, r = i % C2HP;
            int j = r >> 6, oo = r & 63;
            int o = pass * 64 + oo;
            float raw = g_h[((size_t)(b * NN + n0 + g) * J1 + j) * O1 + o];
            float v = g_bn1a[o] * raw + g_bn1b[o];
            v = v > 0.f ? v : 0.01f * v;
            int cl = oo >> 1;
            int k  = (oo & 1) * J1 + j;
            hp2[(cl * KK + k) * RPAD + g] = v;
        }
        __syncthreads();

        if (pass == 0) {                        // A: constant-channel GEMV
            for (int c = 0; c < DD; c += 8) {
                float w8[8];
#pragma unroll
                for (int q = 0; q < 8; q++) w8[q] = g_w2a[(c + q) * O2C + o2];
#pragma unroll
                for (int q = 0; q < 8; q++) {
                    ull wv = dup2(w8[q]);
                    const float* xr = &xs[(c + q) * G2P];
#pragma unroll
                    for (int p = 0; p < G2P / 2; p++)
                        acc[p] = fma2(*(const ull*)&xr[2 * p], wv, acc[p]);
                }
            }
        }
        // B: diff-channel ee conv (16 channels this pass)
        for (int dcl = 0; dcl < 16; dcl++) {
            const float* wrow = &g_w2t[((pass * 16 + dcl) * KK) * O2C + o2];
            const float* er = &ed2[dcl * KK * RPAD];
#pragma unroll
            for (int sb = 0; sb < KK; sb += 10) {
                ull wd10[10];
#pragma unroll
                for (int q = 0; q < 10; q++) wd10[q] = dup2(wrow[(sb + q) * O2C]);
#pragma unroll
                for (int q = 0; q < 10; q++) {
                    const float* row = &er[(sb + q) * RPAD];
#pragma unroll
                    for (int p = 0; p < G2P / 2; p++)
                        acc[p] = fma2(*(const ull*)&row[2 * p], wd10[q], acc[p]);
                }
            }
        }
        // C: inte (hp) conv (32 channels this pass)
        for (int cl = 0; cl < 32; cl++) {
            const float* wrow = &g_w2c[((pass * 32 + cl) * KK) * O2C + o2];
            const float* hr = &hp2[cl * KK * RPAD];
#pragma unroll
            for (int sb = 0; sb < KK; sb += 10) {
                ull wd10[10];
#pragma unroll
                for (int q = 0; q < 10; q++) wd10[q] = dup2(wrow[(sb + q) * O2C]);
#pragma unroll
                for (int q = 0; q < 10; q++) {
                    const float* row = &hr[(sb + q) * RPAD];
#pragma unroll
                    for (int p = 0; p < G2P / 2; p++)
                        acc[p] = fma2(*(const ull*)&row[2 * p], wd10[q], acc[p]);
                }
            }
        }
    }

    float bias = b2[o2];
    float s1 = 0.f, s2 = 0.f;
#pragma unroll
    for (int p = 0; p < G2P / 2; p++) {
        float2 v = unpk(acc[p]);
        float yx = v.x + bias, yy = v.y + bias;
        g_y[(b * NN + n0 + 2 * p)     * O2C + o2] = yx;
        g_y[(b * NN + n0 + 2 * p + 1) * O2C + o2] = yy;
        s1 += yx + yy; s2 += yx * yx + yy * yy;
    }
    g_q1[blockIdx.x * O2C + o2] = s1;
    g_q2[blockIdx.x * O2C + o2] = s2;
}

// ---------------- BN2 finalize ----------------
__global__ void k_bn2fin(const float* __restrict__ gamma, const float* __restrict__ beta) {
    int o = blockIdx.x;
    int tid = threadIdx.x;
    float s = 0.f, s2 = 0.f;
    for (int blk = tid; blk < NB2; blk += 256) {
        s  += g_q1[blk * O2C + o];
        s2 += g_q2[blk * O2C + o];
    }
    __shared__ float rs[256], rs2[256];
    rs[tid] = s; rs2[tid] = s2;
    __syncthreads();
    for (int t = 128; t > 0; t >>= 1) {
        if (tid < t) { rs[tid] += rs[tid + t]; rs2[tid] += rs2[tid + t]; }
        __syncthreads();
    }
    if (tid == 0) {
        float cnt  = (float)(BB * NN);
        float mean = rs[0] / cnt;
        float var  = rs2[0] / cnt - mean * mean;
        float a    = gamma[o] * rsqrtf(var + 1e-5f);
        g_bn2a[o] = a;
        g_bn2b[o] = beta[o] - mean * a;
    }
}

// ---------------- output: tiled transpose, coalesced both sides --------------
// block = (b, 32-point chunk); smem tile 32x(256+1)
__global__ void __launch_bounds__(256) k_out(float* __restrict__ out) {
    __shared__ float sy[32 * 257];
    int b  = blockIdx.x >> 6;
    int n0 = (blockIdx.x & 63) * 32;
    int tid = threadIdx.x;

    // load: coalesced over o2, apply BN2+relu
    for (int it = 0; it < 32; it++) {
        int g = it, o2 = tid;
        float v = g_y[(b * NN + n0 + g) * O2C + o2];
        v = g_bn2a[o2] * v + g_bn2b[o2];
        sy[g * 257 + o2] = v > 0.f ? v : 0.f;
    }
    __syncthreads();
    // store: row = o2 → out[b][o2>>1][(o2&1)*2048 + n0+g], coalesced over g
    float* ob = out + (size_t)b * 524288;
    for (int it = 0; it < 32; it++) {
        int row = (tid >> 5) + it * 8;       // o2
        int g   = tid & 31;
        ob[(row >> 1) * 4096 + (row & 1) * 2048 + n0 + g] = sy[g * 257 + row];
    }
}

// ---------------- launch ----------------
extern "C" void kernel_launch(void* const* d_in, const int* in_sizes, int n_in,
                              void* d_out, int out_size) {
    const float* x   = (const float*)d_in[0];
    const float* w1  = (const float*)d_in[1];
    const float* b1  = (const float*)d_in[2];
    const float* g1  = (const float*)d_in[3];
    const float* be1 = (const float*)d_in[4];
    const float* w2  = (const float*)d_in[5];
    const float* b2  = (const float*)d_in[6];
    const float* g2  = (const float*)d_in[7];
    const float* be2 = (const float*)d_in[8];
    float* out = (float*)d_out;

    static int attr_done = 0;
    int smem1 = (DD * G1 + DD * KK * G1 + 8 * W1SLAB) * (int)sizeof(float);   // ~112KB
    int smem2 = (DD * G2P + (C2ED + C2HP) * RPAD) * (int)sizeof(float);       // ~73KB
    if (!attr_done) {
        cudaFuncSetAttribute(k_conv1, cudaFuncAttributeMaxDynamicSharedMemorySize, smem1);
        cudaFuncSetAttribute(k_conv2, cudaFuncAttributeMaxDynamicSharedMemorySize, smem2);
        attr_done = 1;
    }

    // launch order chosen so conv1 is the 4th launch (ncu captures launch #4)
    k_tw1x<<<(O1 * CC * T1 + 255) / 256, 256>>>(w1);
    k_sq  <<<(BB * NN + 255) / 256, 256>>>(x);
    k_knn <<<BB * NN / GN, 256>>>(x);
    k_conv1<<<NB1, 256, smem1>>>(x, b1);
    k_tw2x<<<(O2C * CC * SS + 255) / 256, 256>>>(w2);
    k_bn1fin<<<O1, 256>>>(g1, be1);
    k_conv2<<<NB2, 256, smem2>>>(x, b2);
    k_bn2fin<<<O2C, 256>>>(g2, be2);
    k_out <<<BB * 64, 256>>>(out);
}